// round 1
// baseline (speedup 1.0000x reference)
#include <cuda_runtime.h>
#include <cuda_bf16.h>
#include <math.h>

#define N_NODES  100000
#define N_EDGES  1600000
#define HIDDEN   128
#define N_GRAPHS 256
#define L1DIM    64

// ---------------- scratch (device globals; no allocations allowed) ----------
__device__ float g_feat0[N_NODES * HIDDEN];   // h (embed out / layer2 out)
__device__ float g_feat1[N_NODES * HIDDEN];   // layer1 out
__device__ float g_agg  [N_NODES * HIDDEN];   // scatter accumulator
__device__ float g_pool [N_GRAPHS * HIDDEN];
__device__ float g_cnt  [N_GRAPHS];
__device__ float g_w1relT [HIDDEN * HIDDEN];  // transposed weights [k][o]
__device__ float g_w1rootT[HIDDEN * HIDDEN];
__device__ float g_w2relT [HIDDEN * HIDDEN];
__device__ float g_w2rootT[HIDDEN * HIDDEN];

// ---------------- small helpers --------------------------------------------
__device__ __forceinline__ float warp_sum(float v) {
    #pragma unroll
    for (int m = 16; m > 0; m >>= 1) v += __shfl_xor_sync(0xffffffffu, v, m);
    return v;
}

// ---------------- transpose weights [o][k] -> [k][o] ------------------------
__global__ void transpose_weights_kernel(const float* __restrict__ w1r,
                                         const float* __restrict__ w1o,
                                         const float* __restrict__ w2r,
                                         const float* __restrict__ w2o) {
    int i = blockIdx.x * blockDim.x + threadIdx.x;
    if (i < HIDDEN * HIDDEN) {
        int o = i >> 7, k = i & 127;
        int t = k * HIDDEN + o;
        g_w1relT [t] = w1r[i];
        g_w1rootT[t] = w1o[i];
        g_w2relT [t] = w2r[i];
        g_w2rootT[t] = w2o[i];
    }
}

// ---------------- embedding with max_norm=1 ---------------------------------
// warp per node; 4 f32 per lane (one float4)
__global__ void embed_kernel(const int* __restrict__ x,
                             const float* __restrict__ emb_w) {
    int warp = (blockIdx.x * blockDim.x + threadIdx.x) >> 5;
    int lane = threadIdx.x & 31;
    if (warp >= N_NODES) return;
    int idx = x[warp];
    const float4* row = (const float4*)(emb_w + (size_t)idx * HIDDEN);
    float4 v = __ldg(&row[lane]);
    float ss = v.x*v.x + v.y*v.y + v.z*v.z + v.w*v.w;
    ss = warp_sum(ss);
    float norm = sqrtf(ss);
    float scale = fminf(1.0f, 1.0f / (norm + 1e-7f));
    float4 o = make_float4(v.x*scale, v.y*scale, v.z*scale, v.w*scale);
    ((float4*)(g_feat0 + (size_t)warp * HIDDEN))[lane] = o;
}

// ---------------- zero kernels ----------------------------------------------
__global__ void zero_agg_kernel() {
    float4* p = (float4*)g_agg;
    int n4 = N_NODES * HIDDEN / 4;
    for (int i = blockIdx.x * blockDim.x + threadIdx.x; i < n4;
         i += gridDim.x * blockDim.x)
        p[i] = make_float4(0.f, 0.f, 0.f, 0.f);
}
__global__ void zero_pool_kernel() {
    int i = threadIdx.x;
    for (int j = i; j < N_GRAPHS * HIDDEN; j += blockDim.x) g_pool[j] = 0.f;
    if (i < N_GRAPHS) g_cnt[i] = 0.f;
}

// ---------------- edge scatter: agg[dst] += h[src] * ew ---------------------
// warp per edge, vectorized red.global.add.v4.f32
__global__ void scatter_kernel(const int* __restrict__ edge_index,
                               const float* __restrict__ ew,
                               const float* __restrict__ h) {
    int warp = (blockIdx.x * blockDim.x + threadIdx.x) >> 5;
    int lane = threadIdx.x & 31;
    if (warp >= N_EDGES) return;
    int src = edge_index[warp];
    int dst = edge_index[N_EDGES + warp];
    float w = ew[warp];
    float4 v = __ldg(((const float4*)(h + (size_t)src * HIDDEN)) + lane);
    v.x *= w; v.y *= w; v.z *= w; v.w *= w;
    float* dp = g_agg + (size_t)dst * HIDDEN + lane * 4;
    asm volatile("red.global.add.v4.f32 [%0], {%1,%2,%3,%4};"
                 :: "l"(dp), "f"(v.x), "f"(v.y), "f"(v.z), "f"(v.w)
                 : "memory");
}

// ---------------- dual GEMM + bias + relu -----------------------------------
// out[n][o] = relu( sum_k agg[n][k]*wrelT[k][o] + h[n][k]*wrootT[k][o] + b[o] )
// warp handles 4 nodes; lane owns outputs o = lane*4..lane*4+3 (float4)
__global__ void __launch_bounds__(256)
linear_kernel(const float* __restrict__ agg,
              const float* __restrict__ hin,
              const float* __restrict__ wrelT,
              const float* __restrict__ wrootT,
              const float* __restrict__ bias,
              float* __restrict__ out) {
    int warp = (blockIdx.x * blockDim.x + threadIdx.x) >> 5;
    int lane = threadIdx.x & 31;
    int n0 = warp * 4;                     // N_NODES % 4 == 0
    if (n0 >= N_NODES) return;

    const float4* wr4 = (const float4*)wrelT;
    const float4* wo4 = (const float4*)wrootT;

    float a[4][4], hh[4][4];
    #pragma unroll
    for (int nn = 0; nn < 4; nn++) {
        const float* ar = agg + (size_t)(n0 + nn) * HIDDEN;
        const float* hr = hin + (size_t)(n0 + nn) * HIDDEN;
        #pragma unroll
        for (int q = 0; q < 4; q++) {
            a [nn][q] = ar[q * 32 + lane];
            hh[nn][q] = hr[q * 32 + lane];
        }
    }

    float4 acc[4];
    #pragma unroll
    for (int nn = 0; nn < 4; nn++) acc[nn] = make_float4(0.f, 0.f, 0.f, 0.f);

    #pragma unroll
    for (int q = 0; q < 4; q++) {
        #pragma unroll 8
        for (int k2 = 0; k2 < 32; k2++) {
            int k = q * 32 + k2;
            float4 wr = __ldg(&wr4[k * 32 + lane]);
            float4 wo = __ldg(&wo4[k * 32 + lane]);
            #pragma unroll
            for (int nn = 0; nn < 4; nn++) {
                float ak = __shfl_sync(0xffffffffu, a [nn][q], k2);
                float hk = __shfl_sync(0xffffffffu, hh[nn][q], k2);
                acc[nn].x += ak * wr.x + hk * wo.x;
                acc[nn].y += ak * wr.y + hk * wo.y;
                acc[nn].z += ak * wr.z + hk * wo.z;
                acc[nn].w += ak * wr.w + hk * wo.w;
            }
        }
    }

    float4 bb = __ldg(((const float4*)bias) + lane);
    #pragma unroll
    for (int nn = 0; nn < 4; nn++) {
        float4 o;
        o.x = fmaxf(acc[nn].x + bb.x, 0.f);
        o.y = fmaxf(acc[nn].y + bb.y, 0.f);
        o.z = fmaxf(acc[nn].z + bb.z, 0.f);
        o.w = fmaxf(acc[nn].w + bb.w, 0.f);
        ((float4*)(out + (size_t)(n0 + nn) * HIDDEN))[lane] = o;
    }
}

// ---------------- segmented mean-pool (batch is sorted) ---------------------
#define POOL_CHUNK 512
__global__ void pool_kernel(const int* __restrict__ batch,
                            const float* __restrict__ h) {
    int n0 = blockIdx.x * POOL_CHUNK;
    int n1 = min(n0 + POOL_CHUNK, N_NODES);
    if (n0 >= N_NODES) return;
    int d = threadIdx.x;                   // 128 threads: one per dim
    float acc = 0.f, cnt = 0.f;
    int cur = batch[n0];
    for (int n = n0; n < n1; n++) {
        int b = batch[n];                  // uniform across block
        if (b != cur) {
            atomicAdd(&g_pool[cur * HIDDEN + d], acc);
            if (d == 0) atomicAdd(&g_cnt[cur], cnt);
            acc = 0.f; cnt = 0.f; cur = b;
        }
        acc += h[(size_t)n * HIDDEN + d];
        cnt += 1.f;
    }
    atomicAdd(&g_pool[cur * HIDDEN + d], acc);
    if (d == 0) atomicAdd(&g_cnt[cur], cnt);
}

// ---------------- classifier: mean -> fc64 relu -> fc2 -> softmax -----------
// warp per graph; 8 warps/block, 32 blocks
__global__ void __launch_bounds__(256)
classifier_kernel(const float* __restrict__ cls1_w,
                  const float* __restrict__ cls1_b,
                  const float* __restrict__ cls2_w,
                  const float* __restrict__ cls2_b,
                  float* __restrict__ out) {
    __shared__ float s_w1[L1DIM * HIDDEN];     // 32 KB
    __shared__ float s_b1[L1DIM];
    __shared__ float s_w2[2 * L1DIM];
    __shared__ float s_b2[2];

    for (int i = threadIdx.x; i < L1DIM * HIDDEN; i += blockDim.x)
        s_w1[i] = cls1_w[i];
    if (threadIdx.x < L1DIM) s_b1[threadIdx.x] = cls1_b[threadIdx.x];
    if (threadIdx.x < 2 * L1DIM) s_w2[threadIdx.x] = cls2_w[threadIdx.x];
    if (threadIdx.x < 2) s_b2[threadIdx.x] = cls2_b[threadIdx.x];
    __syncthreads();

    int g = blockIdx.x * 8 + (threadIdx.x >> 5);
    int lane = threadIdx.x & 31;
    if (g >= N_GRAPHS) return;

    float c = fmaxf(g_cnt[g], 1.0f);
    float4 p = ((const float4*)(g_pool + g * HIDDEN))[lane];
    float inv = 1.0f / c;
    p.x *= inv; p.y *= inv; p.z *= inv; p.w *= inv;

    float z1a = 0.f, z1b = 0.f;   // lane l holds z1[l] and z1[32+l]
    const float4* w14 = (const float4*)s_w1;
    #pragma unroll 4
    for (int j = 0; j < L1DIM; j++) {
        float4 w = w14[j * 32 + lane];
        float s = p.x*w.x + p.y*w.y + p.z*w.z + p.w*w.w;
        s = warp_sum(s);
        float v = fmaxf(s + s_b1[j], 0.f);
        if (j < 32) { if (lane == j)      z1a = v; }
        else        { if (lane == j - 32) z1b = v; }
    }

    float t0 = s_w2[lane] * z1a + s_w2[lane + 32] * z1b;
    float t1 = s_w2[L1DIM + lane] * z1a + s_w2[L1DIM + lane + 32] * z1b;
    t0 = warp_sum(t0);
    t1 = warp_sum(t1);
    if (lane == 0) {
        float z0 = t0 + s_b2[0];
        float z1 = t1 + s_b2[1];
        float m = fmaxf(z0, z1);
        float e0 = expf(z0 - m), e1 = expf(z1 - m);
        float d = e0 + e1;
        out[g * 2 + 0] = e0 / d;
        out[g * 2 + 1] = e1 / d;
    }
}

// ---------------- launch ----------------------------------------------------
extern "C" void kernel_launch(void* const* d_in, const int* in_sizes, int n_in,
                              void* d_out, int out_size) {
    const int*   x       = (const int*)  d_in[0];
    const int*   eidx    = (const int*)  d_in[1];
    const float* eweight = (const float*)d_in[2];
    const int*   batch   = (const int*)  d_in[3];
    const float* emb_w   = (const float*)d_in[4];
    const float* w1_rel  = (const float*)d_in[5];
    const float* b1_rel  = (const float*)d_in[6];
    const float* w1_root = (const float*)d_in[7];
    const float* w2_rel  = (const float*)d_in[8];
    const float* b2_rel  = (const float*)d_in[9];
    const float* w2_root = (const float*)d_in[10];
    const float* cls1_w  = (const float*)d_in[11];
    const float* cls1_b  = (const float*)d_in[12];
    const float* cls2_w  = (const float*)d_in[13];
    const float* cls2_b  = (const float*)d_in[14];
    float* out = (float*)d_out;

    float *p_f0, *p_f1, *p_agg, *p_w1r, *p_w1o, *p_w2r, *p_w2o;
    cudaGetSymbolAddress((void**)&p_f0,  g_feat0);
    cudaGetSymbolAddress((void**)&p_f1,  g_feat1);
    cudaGetSymbolAddress((void**)&p_agg, g_agg);
    cudaGetSymbolAddress((void**)&p_w1r, g_w1relT);
    cudaGetSymbolAddress((void**)&p_w1o, g_w1rootT);
    cudaGetSymbolAddress((void**)&p_w2r, g_w2relT);
    cudaGetSymbolAddress((void**)&p_w2o, g_w2rootT);

    transpose_weights_kernel<<<64, 256>>>(w1_rel, w1_root, w2_rel, w2_root);
    embed_kernel<<<(N_NODES + 7) / 8, 256>>>(x, emb_w);

    // layer 1
    zero_agg_kernel<<<2048, 256>>>();
    scatter_kernel<<<N_EDGES / 8, 256>>>(eidx, eweight, p_f0);
    linear_kernel<<<(N_NODES / 4 + 7) / 8, 256>>>(p_agg, p_f0, p_w1r, p_w1o,
                                                  b1_rel, p_f1);
    // layer 2
    zero_agg_kernel<<<2048, 256>>>();
    scatter_kernel<<<N_EDGES / 8, 256>>>(eidx, eweight, p_f1);
    linear_kernel<<<(N_NODES / 4 + 7) / 8, 256>>>(p_agg, p_f1, p_w2r, p_w2o,
                                                  b2_rel, p_f0);

    // pool + classify
    zero_pool_kernel<<<1, 256>>>();
    pool_kernel<<<(N_NODES + POOL_CHUNK - 1) / POOL_CHUNK, HIDDEN>>>(batch, p_f0);
    classifier_kernel<<<32, 256>>>(cls1_w, cls1_b, cls2_w, cls2_b, out);
}

// round 4
// speedup vs baseline: 1.3534x; 1.3534x over previous
#include <cuda_runtime.h>
#include <cuda_bf16.h>
#include <math.h>

#define N_NODES  100000
#define N_EDGES  1600000
#define HIDDEN   128
#define N_GRAPHS 256
#define L1DIM    64

// ---------------- scratch (device globals; no allocations allowed) ----------
__device__ float g_feat0[N_NODES * HIDDEN];   // h (embed out / layer2 out)
__device__ float g_feat1[N_NODES * HIDDEN];   // layer1 out
__device__ float g_agg  [N_NODES * HIDDEN];   // scatter accumulator
__device__ float g_pool [N_GRAPHS * HIDDEN];
__device__ float g_cnt  [N_GRAPHS];
__device__ float g_w1relT [HIDDEN * HIDDEN];  // transposed weights [k][o]
__device__ float g_w1rootT[HIDDEN * HIDDEN];
__device__ float g_w2relT [HIDDEN * HIDDEN];
__device__ float g_w2rootT[HIDDEN * HIDDEN];

// ---------------- small helpers --------------------------------------------
__device__ __forceinline__ float warp_sum(float v) {
    #pragma unroll
    for (int m = 16; m > 0; m >>= 1) v += __shfl_xor_sync(0xffffffffu, v, m);
    return v;
}

__device__ __forceinline__ unsigned f2tf32(float x) {
    unsigned r;
    asm("cvt.rna.tf32.f32 %0, %1;" : "=r"(r) : "f"(x));
    return r;
}
__device__ __forceinline__ void split_tf32(float x, unsigned& hi, unsigned& lo) {
    hi = f2tf32(x);
    lo = f2tf32(x - __uint_as_float(hi));
}
__device__ __forceinline__ void mma_tf32(float4& c,
                                         const unsigned* a,
                                         unsigned b0, unsigned b1) {
    asm volatile(
        "mma.sync.aligned.m16n8k8.row.col.f32.tf32.tf32.f32 "
        "{%0,%1,%2,%3}, {%4,%5,%6,%7}, {%8,%9}, {%0,%1,%2,%3};\n"
        : "+f"(c.x), "+f"(c.y), "+f"(c.z), "+f"(c.w)
        : "r"(a[0]), "r"(a[1]), "r"(a[2]), "r"(a[3]), "r"(b0), "r"(b1));
}

// ---------------- transpose weights [o][k] -> [k][o] ------------------------
__global__ void transpose_weights_kernel(const float* __restrict__ w1r,
                                         const float* __restrict__ w1o,
                                         const float* __restrict__ w2r,
                                         const float* __restrict__ w2o) {
    int i = blockIdx.x * blockDim.x + threadIdx.x;
    if (i < HIDDEN * HIDDEN) {
        int o = i >> 7, k = i & 127;
        int t = k * HIDDEN + o;
        g_w1relT [t] = w1r[i];
        g_w1rootT[t] = w1o[i];
        g_w2relT [t] = w2r[i];
        g_w2rootT[t] = w2o[i];
    }
}

// ---------------- embedding with max_norm=1 ---------------------------------
__global__ void embed_kernel(const int* __restrict__ x,
                             const float* __restrict__ emb_w) {
    int warp = (blockIdx.x * blockDim.x + threadIdx.x) >> 5;
    int lane = threadIdx.x & 31;
    if (warp >= N_NODES) return;
    int idx = x[warp];
    const float4* row = (const float4*)(emb_w + (size_t)idx * HIDDEN);
    float4 v = __ldg(&row[lane]);
    float ss = v.x*v.x + v.y*v.y + v.z*v.z + v.w*v.w;
    ss = warp_sum(ss);
    float norm = sqrtf(ss);
    float scale = fminf(1.0f, 1.0f / (norm + 1e-7f));
    float4 o = make_float4(v.x*scale, v.y*scale, v.z*scale, v.w*scale);
    ((float4*)(g_feat0 + (size_t)warp * HIDDEN))[lane] = o;
}

// ---------------- zero kernels ----------------------------------------------
__global__ void zero_agg_kernel() {
    float4* p = (float4*)g_agg;
    int n4 = N_NODES * HIDDEN / 4;
    for (int i = blockIdx.x * blockDim.x + threadIdx.x; i < n4;
         i += gridDim.x * blockDim.x)
        p[i] = make_float4(0.f, 0.f, 0.f, 0.f);
}
__global__ void zero_pool_kernel() {
    int i = threadIdx.x;
    for (int j = i; j < N_GRAPHS * HIDDEN; j += blockDim.x) g_pool[j] = 0.f;
    if (i < N_GRAPHS) g_cnt[i] = 0.f;
}

// ---------------- edge scatter: agg[dst] += h[src] * ew ---------------------
__global__ void scatter_kernel(const int* __restrict__ edge_index,
                               const float* __restrict__ ew,
                               const float* __restrict__ h) {
    int warp = (blockIdx.x * blockDim.x + threadIdx.x) >> 5;
    int lane = threadIdx.x & 31;
    if (warp >= N_EDGES) return;
    int src = edge_index[warp];
    int dst = edge_index[N_EDGES + warp];
    float w = ew[warp];
    float4 v = __ldg(((const float4*)(h + (size_t)src * HIDDEN)) + lane);
    v.x *= w; v.y *= w; v.z *= w; v.w *= w;
    float* dp = g_agg + (size_t)dst * HIDDEN + lane * 4;
    asm volatile("red.global.add.v4.f32 [%0], {%1,%2,%3,%4};"
                 :: "l"(dp), "f"(v.x), "f"(v.y), "f"(v.z), "f"(v.w)
                 : "memory");
}

// ---------------- tensor-core dual GEMM + bias + relu -----------------------
// out[n][o] = relu( sum_k agg[n][k]*wrelT[k][o] + hin[n][k]*wrootT[k][o] + b[o])
// Treated as single GEMM: A = [agg | hin] (K=256), B = [wrelT ; wrootT].
// Block: 128 rows x 64 cols. 8 warps = 4(M) x 2(N); warp tile 32x32.
// TF32 3x split for fp32-level accuracy.
#define APAD 20                 // 16 k + 4 pad (keeps 16B alignment)
#define BPAD 68                 // 64 n + 4 pad
#define SMEM_B_FLOATS (256 * BPAD)
#define SMEM_A_FLOATS (2 * 128 * APAD)
#define LIN_SMEM_BYTES ((SMEM_B_FLOATS + SMEM_A_FLOATS) * 4)

__global__ void __launch_bounds__(256, 2)
linear_mma_kernel(const float* __restrict__ agg,
                  const float* __restrict__ hin,
                  const float* __restrict__ wrelT,
                  const float* __restrict__ wrootT,
                  const float* __restrict__ bias,
                  float* __restrict__ out) {
    extern __shared__ float smem[];
    float* sB = smem;                       // [256][BPAD]
    float* sA = smem + SMEM_B_FLOATS;       // [2][128][APAD]

    int tid  = threadIdx.x;
    int lane = tid & 31;
    int warp = tid >> 5;
    int warpM = warp & 3;                   // 0..3 -> 32-row slices
    int warpN = warp >> 2;                  // 0..1 -> 32-col slices

    int tileM = blockIdx.x >> 1;
    int nb    = (blockIdx.x & 1) * 64;      // 0 or 64
    int rowBase = tileM * 128;

    // ---- load B (256 x 64 slice) into smem ----
    #pragma unroll
    for (int it = 0; it < 16; it++) {
        int idx = it * 256 + tid;           // 4096 float4 total
        int k = idx >> 4;
        int q = idx & 15;
        const float* src = (k < 128) ? (wrelT + (size_t)k * 128)
                                     : (wrootT + (size_t)(k - 128) * 128);
        float4 v = __ldg((const float4*)(src + nb) + q);
        *(float4*)(sB + k * BPAD + q * 4) = v;
    }

    // ---- prologue: load A stage 0 ----
    {
        const float* src = agg;             // stage 0 -> k 0..15 of agg
        #pragma unroll
        for (int i = 0; i < 2; i++) {
            int r = (tid >> 2) + i * 64;
            int q = tid & 3;
            int node = rowBase + r;
            float4 v = make_float4(0.f, 0.f, 0.f, 0.f);
            if (node < N_NODES)
                v = __ldg((const float4*)(src + (size_t)node * 128) + q);
            *(float4*)(sA + r * APAD + q * 4) = v;
        }
    }
    __syncthreads();

    float4 acc[2][4];
    #pragma unroll
    for (int mt = 0; mt < 2; mt++)
        #pragma unroll
        for (int j = 0; j < 4; j++)
            acc[mt][j] = make_float4(0.f, 0.f, 0.f, 0.f);

    for (int s = 0; s < 16; s++) {
        // prefetch next stage into registers
        float4 pre[2];
        if (s < 15) {
            int ks = (s + 1) * 16;
            const float* src = (ks < 128) ? agg : hin;
            int koff = ks & 127;
            #pragma unroll
            for (int i = 0; i < 2; i++) {
                int r = (tid >> 2) + i * 64;
                int q = tid & 3;
                int node = rowBase + r;
                pre[i] = make_float4(0.f, 0.f, 0.f, 0.f);
                if (node < N_NODES)
                    pre[i] = __ldg((const float4*)(src + (size_t)node * 128)
                                   + (koff >> 2) + q);
            }
        }

        const float* bufA = sA + (s & 1) * 128 * APAD;
        #pragma unroll
        for (int kk = 0; kk < 16; kk += 8) {
            // A fragments (2 m-tiles)
            unsigned ah[2][4], al[2][4];
            #pragma unroll
            for (int mt = 0; mt < 2; mt++) {
                int rm = warpM * 32 + mt * 16 + (lane >> 2);
                int kc = kk + (lane & 3);
                float a0 = bufA[rm * APAD + kc];
                float a1 = bufA[(rm + 8) * APAD + kc];
                float a2 = bufA[rm * APAD + kc + 4];
                float a3 = bufA[(rm + 8) * APAD + kc + 4];
                split_tf32(a0, ah[mt][0], al[mt][0]);
                split_tf32(a1, ah[mt][1], al[mt][1]);
                split_tf32(a2, ah[mt][2], al[mt][2]);
                split_tf32(a3, ah[mt][3], al[mt][3]);
            }
            // B fragments (4 n-subtiles)
            unsigned bh[4][2], bl[4][2];
            int kb = s * 16 + kk;
            #pragma unroll
            for (int j = 0; j < 4; j++) {
                int cn = warpN * 32 + j * 8 + (lane >> 2);
                float b0 = sB[(kb + (lane & 3)) * BPAD + cn];
                float b1 = sB[(kb + 4 + (lane & 3)) * BPAD + cn];
                split_tf32(b0, bh[j][0], bl[j][0]);
                split_tf32(b1, bh[j][1], bl[j][1]);
            }
            // 3xTF32 mma
            #pragma unroll
            for (int mt = 0; mt < 2; mt++)
                #pragma unroll
                for (int j = 0; j < 4; j++) {
                    mma_tf32(acc[mt][j], al[mt], bh[j][0], bh[j][1]);
                    mma_tf32(acc[mt][j], ah[mt], bl[j][0], bl[j][1]);
                    mma_tf32(acc[mt][j], ah[mt], bh[j][0], bh[j][1]);
                }
        }

        if (s < 15) {
            float* nbuf = sA + ((s + 1) & 1) * 128 * APAD;
            #pragma unroll
            for (int i = 0; i < 2; i++) {
                int r = (tid >> 2) + i * 64;
                int q = tid & 3;
                *(float4*)(nbuf + r * APAD + q * 4) = pre[i];
            }
        }
        __syncthreads();
    }

    // ---- epilogue: bias + relu + store ----
    #pragma unroll
    for (int mt = 0; mt < 2; mt++) {
        #pragma unroll
        for (int j = 0; j < 4; j++) {
            int col = nb + warpN * 32 + j * 8 + (lane & 3) * 2;
            float b0 = __ldg(bias + col);
            float b1 = __ldg(bias + col + 1);
            int row0 = rowBase + warpM * 32 + mt * 16 + (lane >> 2);
            int row1 = row0 + 8;
            float4 c = acc[mt][j];
            if (row0 < N_NODES) {
                float2 v;
                v.x = fmaxf(c.x + b0, 0.f);
                v.y = fmaxf(c.y + b1, 0.f);
                *(float2*)(out + (size_t)row0 * 128 + col) = v;
            }
            if (row1 < N_NODES) {
                float2 v;
                v.x = fmaxf(c.z + b0, 0.f);
                v.y = fmaxf(c.w + b1, 0.f);
                *(float2*)(out + (size_t)row1 * 128 + col) = v;
            }
        }
    }
}

// ---------------- segmented mean-pool (batch is sorted) ---------------------
#define POOL_CHUNK 256
__global__ void pool_kernel(const int* __restrict__ batch,
                            const float* __restrict__ h) {
    int n0 = blockIdx.x * POOL_CHUNK;
    int n1 = min(n0 + POOL_CHUNK, N_NODES);
    if (n0 >= N_NODES) return;
    int d = threadIdx.x;                   // 128 threads: one per dim
    float acc = 0.f, cnt = 0.f;
    int cur = batch[n0];
    for (int n = n0; n < n1; n++) {
        int b = batch[n];                  // uniform across block
        if (b != cur) {
            atomicAdd(&g_pool[cur * HIDDEN + d], acc);
            if (d == 0) atomicAdd(&g_cnt[cur], cnt);
            acc = 0.f; cnt = 0.f; cur = b;
        }
        acc += h[(size_t)n * HIDDEN + d];
        cnt += 1.f;
    }
    atomicAdd(&g_pool[cur * HIDDEN + d], acc);
    if (d == 0) atomicAdd(&g_cnt[cur], cnt);
}

// ---------------- classifier: mean -> fc64 relu -> fc2 -> softmax -----------
__global__ void __launch_bounds__(256)
classifier_kernel(const float* __restrict__ cls1_w,
                  const float* __restrict__ cls1_b,
                  const float* __restrict__ cls2_w,
                  const float* __restrict__ cls2_b,
                  float* __restrict__ out) {
    __shared__ float s_w1[L1DIM * HIDDEN];
    __shared__ float s_b1[L1DIM];
    __shared__ float s_w2[2 * L1DIM];
    __shared__ float s_b2[2];

    for (int i = threadIdx.x; i < L1DIM * HIDDEN; i += blockDim.x)
        s_w1[i] = cls1_w[i];
    if (threadIdx.x < L1DIM) s_b1[threadIdx.x] = cls1_b[threadIdx.x];
    if (threadIdx.x < 2 * L1DIM) s_w2[threadIdx.x] = cls2_w[threadIdx.x];
    if (threadIdx.x < 2) s_b2[threadIdx.x] = cls2_b[threadIdx.x];
    __syncthreads();

    int g = blockIdx.x * 8 + (threadIdx.x >> 5);
    int lane = threadIdx.x & 31;
    if (g >= N_GRAPHS) return;

    float c = fmaxf(g_cnt[g], 1.0f);
    float4 p = ((const float4*)(g_pool + g * HIDDEN))[lane];
    float inv = 1.0f / c;
    p.x *= inv; p.y *= inv; p.z *= inv; p.w *= inv;

    float z1a = 0.f, z1b = 0.f;
    const float4* w14 = (const float4*)s_w1;
    #pragma unroll 4
    for (int j = 0; j < L1DIM; j++) {
        float4 w = w14[j * 32 + lane];
        float s = p.x*w.x + p.y*w.y + p.z*w.z + p.w*w.w;
        s = warp_sum(s);
        float v = fmaxf(s + s_b1[j], 0.f);
        if (j < 32) { if (lane == j)      z1a = v; }
        else        { if (lane == j - 32) z1b = v; }
    }

    float t0 = s_w2[lane] * z1a + s_w2[lane + 32] * z1b;
    float t1 = s_w2[L1DIM + lane] * z1a + s_w2[L1DIM + lane + 32] * z1b;
    t0 = warp_sum(t0);
    t1 = warp_sum(t1);
    if (lane == 0) {
        float z0 = t0 + s_b2[0];
        float z1 = t1 + s_b2[1];
        float m = fmaxf(z0, z1);
        float e0 = expf(z0 - m), e1 = expf(z1 - m);
        float d = e0 + e1;
        out[g * 2 + 0] = e0 / d;
        out[g * 2 + 1] = e1 / d;
    }
}

// ---------------- launch ----------------------------------------------------
extern "C" void kernel_launch(void* const* d_in, const int* in_sizes, int n_in,
                              void* d_out, int out_size) {
    const int*   x       = (const int*)  d_in[0];
    const int*   eidx    = (const int*)  d_in[1];
    const float* eweight = (const float*)d_in[2];
    const int*   batch   = (const int*)  d_in[3];
    const float* emb_w   = (const float*)d_in[4];
    const float* b1_rel  = (const float*)d_in[6];
    const float* b2_rel  = (const float*)d_in[9];
    const float* cls1_w  = (const float*)d_in[11];
    const float* cls1_b  = (const float*)d_in[12];
    const float* cls2_w  = (const float*)d_in[13];
    const float* cls2_b  = (const float*)d_in[14];
    const float* w1_rel  = (const float*)d_in[5];
    const float* w1_root = (const float*)d_in[7];
    const float* w2_rel  = (const float*)d_in[8];
    const float* w2_root = (const float*)d_in[10];
    float* out = (float*)d_out;

    float *p_f0, *p_f1, *p_agg, *p_w1r, *p_w1o, *p_w2r, *p_w2o;
    cudaGetSymbolAddress((void**)&p_f0,  g_feat0);
    cudaGetSymbolAddress((void**)&p_f1,  g_feat1);
    cudaGetSymbolAddress((void**)&p_agg, g_agg);
    cudaGetSymbolAddress((void**)&p_w1r, g_w1relT);
    cudaGetSymbolAddress((void**)&p_w1o, g_w1rootT);
    cudaGetSymbolAddress((void**)&p_w2r, g_w2relT);
    cudaGetSymbolAddress((void**)&p_w2o, g_w2rootT);

    static int smem_set = 0;
    if (!smem_set) {
        cudaFuncSetAttribute(linear_mma_kernel,
                             cudaFuncAttributeMaxDynamicSharedMemorySize,
                             LIN_SMEM_BYTES);
        smem_set = 1;
    }

    transpose_weights_kernel<<<64, 256>>>(w1_rel, w1_root, w2_rel, w2_root);
    embed_kernel<<<(N_NODES + 7) / 8, 256>>>(x, emb_w);

    int nTiles = (N_NODES + 127) / 128;     // 782
    // layer 1
    zero_agg_kernel<<<2048, 256>>>();
    scatter_kernel<<<N_EDGES / 8, 256>>>(eidx, eweight, p_f0);
    linear_mma_kernel<<<nTiles * 2, 256, LIN_SMEM_BYTES>>>(p_agg, p_f0, p_w1r,
                                                           p_w1o, b1_rel, p_f1);
    // layer 2
    zero_agg_kernel<<<2048, 256>>>();
    scatter_kernel<<<N_EDGES / 8, 256>>>(eidx, eweight, p_f1);
    linear_mma_kernel<<<nTiles * 2, 256, LIN_SMEM_BYTES>>>(p_agg, p_f1, p_w2r,
                                                           p_w2o, b2_rel, p_f0);

    // pool + classify
    zero_pool_kernel<<<1, 256>>>();
    pool_kernel<<<(N_NODES + POOL_CHUNK - 1) / POOL_CHUNK, HIDDEN>>>(batch, p_f0);
    classifier_kernel<<<32, 256>>>(cls1_w, cls1_b, cls2_w, cls2_b, out);
}

// round 5
// speedup vs baseline: 1.4893x; 1.1004x over previous
#include <cuda_runtime.h>
#include <cuda_bf16.h>
#include <math.h>

#define N_NODES  100000
#define N_EDGES  1600000
#define HIDDEN   128
#define N_GRAPHS 256
#define L1DIM    64

// ---------------- scratch (device globals; no allocations allowed) ----------
__device__ float g_feat0[N_NODES * HIDDEN];
__device__ float g_feat1[N_NODES * HIDDEN];
__device__ float g_agg  [N_NODES * HIDDEN];
__device__ float g_pool [N_GRAPHS * HIDDEN];
__device__ float g_cnt  [N_GRAPHS];
// CSR scratch
__device__ int   g_deg     [N_NODES];
__device__ int   g_rowstart[N_NODES + 1];
__device__ int   g_cursor  [N_NODES];
__device__ __align__(16) int2 g_csr[N_EDGES];
// pre-split weights: [o 0..127][k 0..255] (k<128 = rel, k>=128 = root)
__device__ __align__(16) __nv_bfloat16 g_b1hi[HIDDEN * 256];
__device__ __align__(16) __nv_bfloat16 g_b1lo[HIDDEN * 256];
__device__ __align__(16) __nv_bfloat16 g_b2hi[HIDDEN * 256];
__device__ __align__(16) __nv_bfloat16 g_b2lo[HIDDEN * 256];

// ---------------- helpers ----------------------------------------------------
__device__ __forceinline__ float warp_sum(float v) {
    #pragma unroll
    for (int m = 16; m > 0; m >>= 1) v += __shfl_xor_sync(0xffffffffu, v, m);
    return v;
}
__device__ __forceinline__ unsigned packbf(float a, float b) {
    __nv_bfloat162 t = __floats2bfloat162_rn(a, b);   // low = a (even k)
    return *reinterpret_cast<unsigned*>(&t);
}
__device__ __forceinline__ void mma_bf16(float4& c, const unsigned* a,
                                         unsigned b0, unsigned b1) {
    asm volatile(
        "mma.sync.aligned.m16n8k16.row.col.f32.bf16.bf16.f32 "
        "{%0,%1,%2,%3}, {%4,%5,%6,%7}, {%8,%9}, {%0,%1,%2,%3};\n"
        : "+f"(c.x), "+f"(c.y), "+f"(c.z), "+f"(c.w)
        : "r"(a[0]), "r"(a[1]), "r"(a[2]), "r"(a[3]), "r"(b0), "r"(b1));
}

// ---------------- weight prep: split f32 -> bf16 hi/lo, pack [o][k] ---------
__global__ void prep_weights_kernel(const float* __restrict__ w1r,
                                    const float* __restrict__ w1o,
                                    const float* __restrict__ w2r,
                                    const float* __restrict__ w2o) {
    int i = blockIdx.x * blockDim.x + threadIdx.x;
    if (i >= HIDDEN * HIDDEN) return;
    int o = i >> 7, k = i & 127;
    float v;
    __nv_bfloat16 h;
    v = w1r[i]; h = __float2bfloat16_rn(v);
    g_b1hi[o * 256 + k] = h;
    g_b1lo[o * 256 + k] = __float2bfloat16_rn(v - __bfloat162float(h));
    v = w1o[i]; h = __float2bfloat16_rn(v);
    g_b1hi[o * 256 + 128 + k] = h;
    g_b1lo[o * 256 + 128 + k] = __float2bfloat16_rn(v - __bfloat162float(h));
    v = w2r[i]; h = __float2bfloat16_rn(v);
    g_b2hi[o * 256 + k] = h;
    g_b2lo[o * 256 + k] = __float2bfloat16_rn(v - __bfloat162float(h));
    v = w2o[i]; h = __float2bfloat16_rn(v);
    g_b2hi[o * 256 + 128 + k] = h;
    g_b2lo[o * 256 + 128 + k] = __float2bfloat16_rn(v - __bfloat162float(h));
}

// ---------------- embedding with max_norm=1 ---------------------------------
__global__ void embed_kernel(const int* __restrict__ x,
                             const float* __restrict__ emb_w) {
    int warp = (blockIdx.x * blockDim.x + threadIdx.x) >> 5;
    int lane = threadIdx.x & 31;
    if (warp >= N_NODES) return;
    int idx = x[warp];
    const float4* row = (const float4*)(emb_w + (size_t)idx * HIDDEN);
    float4 v = __ldg(&row[lane]);
    float ss = v.x*v.x + v.y*v.y + v.z*v.z + v.w*v.w;
    ss = warp_sum(ss);
    float scale = fminf(1.0f, 1.0f / (sqrtf(ss) + 1e-7f));
    float4 o = make_float4(v.x*scale, v.y*scale, v.z*scale, v.w*scale);
    ((float4*)(g_feat0 + (size_t)warp * HIDDEN))[lane] = o;
}

// ---------------- zero deg / pool / cnt --------------------------------------
__global__ void zero_misc_kernel() {
    int i = blockIdx.x * blockDim.x + threadIdx.x;
    if (i < N_NODES) g_deg[i] = 0;
    if (i < N_GRAPHS * HIDDEN) g_pool[i] = 0.f;
    if (i < N_GRAPHS) g_cnt[i] = 0.f;
}

// ---------------- CSR build ---------------------------------------------------
__global__ void hist_kernel(const int* __restrict__ eidx) {
    int e = blockIdx.x * blockDim.x + threadIdx.x;
    if (e < N_EDGES) atomicAdd(&g_deg[eidx[N_EDGES + e]], 1);
}

#define SCAN_CH ((N_NODES + 1023) / 1024)
__global__ void scan_kernel() {
    __shared__ int s[1024];
    int t = threadIdx.x;
    int base = t * SCAN_CH;
    int sum = 0;
    for (int i = 0; i < SCAN_CH; i++) {
        int j = base + i;
        if (j < N_NODES) sum += g_deg[j];
    }
    s[t] = sum;
    __syncthreads();
    for (int off = 1; off < 1024; off <<= 1) {
        int v = (t >= off) ? s[t - off] : 0;
        __syncthreads();
        s[t] += v;
        __syncthreads();
    }
    int run = (t == 0) ? 0 : s[t - 1];
    for (int i = 0; i < SCAN_CH; i++) {
        int j = base + i;
        if (j < N_NODES) {
            g_rowstart[j] = run;
            g_cursor[j]   = run;
            run += g_deg[j];
        }
    }
    if (t == 1023) g_rowstart[N_NODES] = run;
}

__global__ void reorder_kernel(const int* __restrict__ eidx,
                               const float* __restrict__ ew) {
    int e = blockIdx.x * blockDim.x + threadIdx.x;
    if (e >= N_EDGES) return;
    int dst = eidx[N_EDGES + e];
    int pos = atomicAdd(&g_cursor[dst], 1);
    g_csr[pos] = make_int2(eidx[e], __float_as_int(ew[e]));
}

// ---------------- CSR aggregation: agg[i] = sum_{e in-edges} h[src]*w --------
#define ECHUNK 64
__global__ void __launch_bounds__(128)
agg_csr_kernel(const float* __restrict__ h) {
    __shared__ int2 s_e[ECHUNK];
    int node = blockIdx.x;
    int t = threadIdx.x;
    int s0 = g_rowstart[node], s1 = g_rowstart[node + 1];
    float a0 = 0.f, a1 = 0.f, a2 = 0.f, a3 = 0.f;
    for (int base = s0; base < s1; base += ECHUNK) {
        int m = min(ECHUNK, s1 - base);
        if (t < m) s_e[t] = g_csr[base + t];
        __syncthreads();
        int i = 0;
        for (; i + 3 < m; i += 4) {
            int2 e0 = s_e[i], e1 = s_e[i+1], e2 = s_e[i+2], e3 = s_e[i+3];
            a0 += __ldg(h + (size_t)e0.x * HIDDEN + t) * __int_as_float(e0.y);
            a1 += __ldg(h + (size_t)e1.x * HIDDEN + t) * __int_as_float(e1.y);
            a2 += __ldg(h + (size_t)e2.x * HIDDEN + t) * __int_as_float(e2.y);
            a3 += __ldg(h + (size_t)e3.x * HIDDEN + t) * __int_as_float(e3.y);
        }
        for (; i < m; i++) {
            int2 e = s_e[i];
            a0 += __ldg(h + (size_t)e.x * HIDDEN + t) * __int_as_float(e.y);
        }
        __syncthreads();
    }
    g_agg[(size_t)node * HIDDEN + t] = (a0 + a1) + (a2 + a3);
}

// ---------------- bf16 split (3-pass) tensor-core dual GEMM ------------------
// out = relu([agg | hin](100k x 256) @ B(256 x 128) + bias)
// Block: 128 rows x 64 cols; 8 warps = 4(M) x 2(N); warp tile 32x32.
#define SB_COL_BF16   264                    // 256 k + 8 pad
#define SB_PLANE_BF16 (64 * SB_COL_BF16)     // 16896
#define SA_ROW_W      9                      // 8 data words (16 bf16) + 1 pad
#define SA_PLANE_W    (128 * SA_ROW_W)       // 1152
#define SA_BUF_W      (2 * SA_PLANE_W)       // hi + lo
#define GEMM_SMEM_BYTES (2 * SB_PLANE_BF16 * 2 + 2 * SA_BUF_W * 4)  // 86016

__global__ void __launch_bounds__(256, 2)
linear_bf16_kernel(const float* __restrict__ agg,
                   const float* __restrict__ hin,
                   const __nv_bfloat16* __restrict__ bhi,
                   const __nv_bfloat16* __restrict__ blo,
                   const float* __restrict__ bias,
                   float* __restrict__ out) {
    extern __shared__ char smem_raw[];
    __nv_bfloat16* sBhi = (__nv_bfloat16*)smem_raw;
    __nv_bfloat16* sBlo = sBhi + SB_PLANE_BF16;
    unsigned* sA = (unsigned*)(smem_raw + 2 * SB_PLANE_BF16 * 2);

    int tid = threadIdx.x, lane = tid & 31, warp = tid >> 5;
    int warpM = warp & 3, warpN = warp >> 2;
    int tileM = blockIdx.x >> 1;
    int nb = (blockIdx.x & 1) * 64;
    int rowBase = tileM * 128;

    // ---- load B 64-col slice (hi+lo) ----
    const float4* srcHi = (const float4*)(bhi + (size_t)nb * 256);
    const float4* srcLo = (const float4*)(blo + (size_t)nb * 256);
    #pragma unroll
    for (int it = 0; it < 8; it++) {
        int idx = it * 256 + tid;
        int col = idx >> 5, q = idx & 31;
        float4 v = __ldg(srcHi + col * 32 + q);
        *(float4*)((char*)sBhi + col * (SB_COL_BF16 * 2) + q * 16) = v;
        float4 w = __ldg(srcLo + col * 32 + q);
        *(float4*)((char*)sBlo + col * (SB_COL_BF16 * 2) + q * 16) = w;
    }

    float4 cur[2], pre[2];
    // ---- A stage loader: stage s covers k = s*16 .. s*16+15 ----
    auto loadA = [&](int s, float4* dst) {
        const float* src = (s * 16 < 128) ? agg : hin;
        int koff = (s * 16) & 127;
        #pragma unroll
        for (int i = 0; i < 2; i++) {
            int r = (tid >> 2) + i * 64, q = tid & 3;
            int node = rowBase + r;
            dst[i] = make_float4(0.f, 0.f, 0.f, 0.f);
            if (node < N_NODES)
                dst[i] = __ldg((const float4*)(src + (size_t)node * 128 + koff) + q);
        }
    };
    auto storeA = [&](int buf, const float4* v4) {
        unsigned* hi = sA + buf * SA_BUF_W;
        unsigned* lo = hi + SA_PLANE_W;
        #pragma unroll
        for (int i = 0; i < 2; i++) {
            int r = (tid >> 2) + i * 64, q = tid & 3;
            float4 v = v4[i];
            float hx = __bfloat162float(__float2bfloat16_rn(v.x));
            float hy = __bfloat162float(__float2bfloat16_rn(v.y));
            float hz = __bfloat162float(__float2bfloat16_rn(v.z));
            float hw = __bfloat162float(__float2bfloat16_rn(v.w));
            hi[r * SA_ROW_W + q * 2]     = packbf(v.x, v.y);
            hi[r * SA_ROW_W + q * 2 + 1] = packbf(v.z, v.w);
            lo[r * SA_ROW_W + q * 2]     = packbf(v.x - hx, v.y - hy);
            lo[r * SA_ROW_W + q * 2 + 1] = packbf(v.z - hz, v.w - hw);
        }
    };

    loadA(0, cur);
    storeA(0, cur);
    __syncthreads();

    float4 acc[2][4];
    #pragma unroll
    for (int mt = 0; mt < 2; mt++)
        #pragma unroll
        for (int j = 0; j < 4; j++)
            acc[mt][j] = make_float4(0.f, 0.f, 0.f, 0.f);

    const unsigned* Bh32 = (const unsigned*)sBhi;
    const unsigned* Bl32 = (const unsigned*)sBlo;

    for (int s = 0; s < 16; s++) {
        if (s < 15) loadA(s + 1, pre);

        const unsigned* Ahi = sA + (s & 1) * SA_BUF_W;
        const unsigned* Alo = Ahi + SA_PLANE_W;

        unsigned ah[2][4], al[2][4];
        #pragma unroll
        for (int mt = 0; mt < 2; mt++) {
            int r0 = warpM * 32 + mt * 16 + (lane >> 2);
            int w0 = lane & 3;
            ah[mt][0] = Ahi[r0 * SA_ROW_W + w0];
            ah[mt][1] = Ahi[(r0 + 8) * SA_ROW_W + w0];
            ah[mt][2] = Ahi[r0 * SA_ROW_W + w0 + 4];
            ah[mt][3] = Ahi[(r0 + 8) * SA_ROW_W + w0 + 4];
            al[mt][0] = Alo[r0 * SA_ROW_W + w0];
            al[mt][1] = Alo[(r0 + 8) * SA_ROW_W + w0];
            al[mt][2] = Alo[r0 * SA_ROW_W + w0 + 4];
            al[mt][3] = Alo[(r0 + 8) * SA_ROW_W + w0 + 4];
        }
        unsigned bh[4][2], bl[4][2];
        #pragma unroll
        for (int j = 0; j < 4; j++) {
            int c = warpN * 32 + j * 8 + (lane >> 2);
            int w = c * (SB_COL_BF16 / 2) + s * 8 + (lane & 3);
            bh[j][0] = Bh32[w];
            bh[j][1] = Bh32[w + 4];
            bl[j][0] = Bl32[w];
            bl[j][1] = Bl32[w + 4];
        }
        #pragma unroll
        for (int mt = 0; mt < 2; mt++)
            #pragma unroll
            for (int j = 0; j < 4; j++) {
                mma_bf16(acc[mt][j], al[mt], bh[j][0], bh[j][1]);
                mma_bf16(acc[mt][j], ah[mt], bl[j][0], bl[j][1]);
                mma_bf16(acc[mt][j], ah[mt], bh[j][0], bh[j][1]);
            }

        if (s < 15) storeA((s + 1) & 1, pre);
        __syncthreads();
    }

    // ---- epilogue: bias + relu + store ----
    #pragma unroll
    for (int mt = 0; mt < 2; mt++) {
        #pragma unroll
        for (int j = 0; j < 4; j++) {
            int col = nb + warpN * 32 + j * 8 + (lane & 3) * 2;
            float b0 = __ldg(bias + col);
            float b1 = __ldg(bias + col + 1);
            int row0 = rowBase + warpM * 32 + mt * 16 + (lane >> 2);
            int row1 = row0 + 8;
            float4 c = acc[mt][j];
            if (row0 < N_NODES) {
                float2 v;
                v.x = fmaxf(c.x + b0, 0.f);
                v.y = fmaxf(c.y + b1, 0.f);
                *(float2*)(out + (size_t)row0 * 128 + col) = v;
            }
            if (row1 < N_NODES) {
                float2 v;
                v.x = fmaxf(c.z + b0, 0.f);
                v.y = fmaxf(c.w + b1, 0.f);
                *(float2*)(out + (size_t)row1 * 128 + col) = v;
            }
        }
    }
}

// ---------------- segmented mean-pool (batch is sorted) ---------------------
#define POOL_CHUNK 256
__global__ void pool_kernel(const int* __restrict__ batch,
                            const float* __restrict__ h) {
    int n0 = blockIdx.x * POOL_CHUNK;
    int n1 = min(n0 + POOL_CHUNK, N_NODES);
    if (n0 >= N_NODES) return;
    int d = threadIdx.x;
    float acc = 0.f, cnt = 0.f;
    int cur = batch[n0];
    for (int n = n0; n < n1; n++) {
        int b = batch[n];
        if (b != cur) {
            atomicAdd(&g_pool[cur * HIDDEN + d], acc);
            if (d == 0) atomicAdd(&g_cnt[cur], cnt);
            acc = 0.f; cnt = 0.f; cur = b;
        }
        acc += h[(size_t)n * HIDDEN + d];
        cnt += 1.f;
    }
    atomicAdd(&g_pool[cur * HIDDEN + d], acc);
    if (d == 0) atomicAdd(&g_cnt[cur], cnt);
}

// ---------------- classifier -------------------------------------------------
__global__ void __launch_bounds__(256)
classifier_kernel(const float* __restrict__ cls1_w,
                  const float* __restrict__ cls1_b,
                  const float* __restrict__ cls2_w,
                  const float* __restrict__ cls2_b,
                  float* __restrict__ out) {
    __shared__ float s_w1[L1DIM * HIDDEN];
    __shared__ float s_b1[L1DIM];
    __shared__ float s_w2[2 * L1DIM];
    __shared__ float s_b2[2];

    for (int i = threadIdx.x; i < L1DIM * HIDDEN; i += blockDim.x)
        s_w1[i] = cls1_w[i];
    if (threadIdx.x < L1DIM) s_b1[threadIdx.x] = cls1_b[threadIdx.x];
    if (threadIdx.x < 2 * L1DIM) s_w2[threadIdx.x] = cls2_w[threadIdx.x];
    if (threadIdx.x < 2) s_b2[threadIdx.x] = cls2_b[threadIdx.x];
    __syncthreads();

    int g = blockIdx.x * 8 + (threadIdx.x >> 5);
    int lane = threadIdx.x & 31;
    if (g >= N_GRAPHS) return;

    float c = fmaxf(g_cnt[g], 1.0f);
    float4 p = ((const float4*)(g_pool + g * HIDDEN))[lane];
    float inv = 1.0f / c;
    p.x *= inv; p.y *= inv; p.z *= inv; p.w *= inv;

    float z1a = 0.f, z1b = 0.f;
    const float4* w14 = (const float4*)s_w1;
    #pragma unroll 4
    for (int j = 0; j < L1DIM; j++) {
        float4 w = w14[j * 32 + lane];
        float s = p.x*w.x + p.y*w.y + p.z*w.z + p.w*w.w;
        s = warp_sum(s);
        float v = fmaxf(s + s_b1[j], 0.f);
        if (j < 32) { if (lane == j)      z1a = v; }
        else        { if (lane == j - 32) z1b = v; }
    }
    float t0 = s_w2[lane] * z1a + s_w2[lane + 32] * z1b;
    float t1 = s_w2[L1DIM + lane] * z1a + s_w2[L1DIM + lane + 32] * z1b;
    t0 = warp_sum(t0);
    t1 = warp_sum(t1);
    if (lane == 0) {
        float z0 = t0 + s_b2[0];
        float z1 = t1 + s_b2[1];
        float m = fmaxf(z0, z1);
        float e0 = expf(z0 - m), e1 = expf(z1 - m);
        float d = e0 + e1;
        out[g * 2 + 0] = e0 / d;
        out[g * 2 + 1] = e1 / d;
    }
}

// ---------------- launch ----------------------------------------------------
extern "C" void kernel_launch(void* const* d_in, const int* in_sizes, int n_in,
                              void* d_out, int out_size) {
    const int*   x       = (const int*)  d_in[0];
    const int*   eidx    = (const int*)  d_in[1];
    const float* eweight = (const float*)d_in[2];
    const int*   batch   = (const int*)  d_in[3];
    const float* emb_w   = (const float*)d_in[4];
    const float* w1_rel  = (const float*)d_in[5];
    const float* b1_rel  = (const float*)d_in[6];
    const float* w1_root = (const float*)d_in[7];
    const float* w2_rel  = (const float*)d_in[8];
    const float* b2_rel  = (const float*)d_in[9];
    const float* w2_root = (const float*)d_in[10];
    const float* cls1_w  = (const float*)d_in[11];
    const float* cls1_b  = (const float*)d_in[12];
    const float* cls2_w  = (const float*)d_in[13];
    const float* cls2_b  = (const float*)d_in[14];
    float* out = (float*)d_out;

    float *p_f0, *p_f1, *p_agg;
    __nv_bfloat16 *p_b1hi, *p_b1lo, *p_b2hi, *p_b2lo;
    cudaGetSymbolAddress((void**)&p_f0,   g_feat0);
    cudaGetSymbolAddress((void**)&p_f1,   g_feat1);
    cudaGetSymbolAddress((void**)&p_agg,  g_agg);
    cudaGetSymbolAddress((void**)&p_b1hi, g_b1hi);
    cudaGetSymbolAddress((void**)&p_b1lo, g_b1lo);
    cudaGetSymbolAddress((void**)&p_b2hi, g_b2hi);
    cudaGetSymbolAddress((void**)&p_b2lo, g_b2lo);

    static int smem_set = 0;
    if (!smem_set) {
        cudaFuncSetAttribute(linear_bf16_kernel,
                             cudaFuncAttributeMaxDynamicSharedMemorySize,
                             GEMM_SMEM_BYTES);
        smem_set = 1;
    }

    prep_weights_kernel<<<64, 256>>>(w1_rel, w1_root, w2_rel, w2_root);
    zero_misc_kernel<<<(N_NODES + 255) / 256, 256>>>();
    embed_kernel<<<(N_NODES + 7) / 8, 256>>>(x, emb_w);

    // CSR build (shared by both layers)
    hist_kernel<<<(N_EDGES + 255) / 256, 256>>>(eidx);
    scan_kernel<<<1, 1024>>>();
    reorder_kernel<<<(N_EDGES + 255) / 256, 256>>>(eidx, eweight);

    int nTiles = (N_NODES + 127) / 128;     // 782
    // layer 1
    agg_csr_kernel<<<N_NODES, 128>>>(p_f0);
    linear_bf16_kernel<<<nTiles * 2, 256, GEMM_SMEM_BYTES>>>(
        p_agg, p_f0, p_b1hi, p_b1lo, b1_rel, p_f1);
    // layer 2
    agg_csr_kernel<<<N_NODES, 128>>>(p_f1);
    linear_bf16_kernel<<<nTiles * 2, 256, GEMM_SMEM_BYTES>>>(
        p_agg, p_f1, p_b2hi, p_b2lo, b2_rel, p_f0);

    // pool + classify
    pool_kernel<<<(N_NODES + POOL_CHUNK - 1) / POOL_CHUNK, HIDDEN>>>(batch, p_f0);
    classifier_kernel<<<32, 256>>>(cls1_w, cls1_b, cls2_w, cls2_b, out);
}

// round 7
// speedup vs baseline: 2.3344x; 1.5675x over previous
#include <cuda_runtime.h>
#include <cuda_bf16.h>
#include <math.h>

#define N_NODES  100000
#define N_EDGES  1600000
#define HIDDEN   128
#define N_GRAPHS 256
#define L1DIM    64

// ---------------- scratch (device globals; no allocations allowed) ----------
__device__ float g_feat0[N_NODES * HIDDEN];
__device__ float g_feat1[N_NODES * HIDDEN];
__device__ float g_agg  [N_NODES * HIDDEN];
__device__ float g_pool [N_GRAPHS * HIDDEN];
__device__ float g_cnt  [N_GRAPHS];
// packed bf16x2 node features for the gather path (25.6 MB, L2-resident)
__device__ __align__(16) unsigned g_hb[N_NODES * 64];
// CSR scratch
__device__ int   g_deg     [N_NODES];
__device__ int   g_rowstart[N_NODES + 1];
__device__ int   g_cursor  [N_NODES];
__device__ int   g_bsum    [256];
__device__ int   g_boff    [256];
__device__ __align__(16) int2 g_csr[N_EDGES];
// pre-split weights: [o 0..127][k 0..255] (k<128 = rel, k>=128 = root)
__device__ __align__(16) __nv_bfloat16 g_b1hi[HIDDEN * 256];
__device__ __align__(16) __nv_bfloat16 g_b1lo[HIDDEN * 256];
__device__ __align__(16) __nv_bfloat16 g_b2hi[HIDDEN * 256];
__device__ __align__(16) __nv_bfloat16 g_b2lo[HIDDEN * 256];

// ---------------- helpers ----------------------------------------------------
__device__ __forceinline__ float warp_sum(float v) {
    #pragma unroll
    for (int m = 16; m > 0; m >>= 1) v += __shfl_xor_sync(0xffffffffu, v, m);
    return v;
}
__device__ __forceinline__ unsigned packbf(float a, float b) {
    __nv_bfloat162 t = __floats2bfloat162_rn(a, b);   // low = a (even dim)
    return *reinterpret_cast<unsigned*>(&t);
}
__device__ __forceinline__ void accum_bf(float4& acc, uint2 u, float w) {
    float2 f0 = __bfloat1622float2(*reinterpret_cast<__nv_bfloat162*>(&u.x));
    float2 f1 = __bfloat1622float2(*reinterpret_cast<__nv_bfloat162*>(&u.y));
    acc.x += f0.x * w;
    acc.y += f0.y * w;
    acc.z += f1.x * w;
    acc.w += f1.y * w;
}
__device__ __forceinline__ void mma_bf16(float4& c, const unsigned* a,
                                         unsigned b0, unsigned b1) {
    asm volatile(
        "mma.sync.aligned.m16n8k16.row.col.f32.bf16.bf16.f32 "
        "{%0,%1,%2,%3}, {%4,%5,%6,%7}, {%8,%9}, {%0,%1,%2,%3};\n"
        : "+f"(c.x), "+f"(c.y), "+f"(c.z), "+f"(c.w)
        : "r"(a[0]), "r"(a[1]), "r"(a[2]), "r"(a[3]), "r"(b0), "r"(b1));
}

// ---------------- weight prep: split f32 -> bf16 hi/lo, pack [o][k] ---------
__global__ void prep_weights_kernel(const float* __restrict__ w1r,
                                    const float* __restrict__ w1o,
                                    const float* __restrict__ w2r,
                                    const float* __restrict__ w2o) {
    int i = blockIdx.x * blockDim.x + threadIdx.x;
    if (i >= HIDDEN * HIDDEN) return;
    int o = i >> 7, k = i & 127;
    float v;
    __nv_bfloat16 h;
    v = w1r[i]; h = __float2bfloat16_rn(v);
    g_b1hi[o * 256 + k] = h;
    g_b1lo[o * 256 + k] = __float2bfloat16_rn(v - __bfloat162float(h));
    v = w1o[i]; h = __float2bfloat16_rn(v);
    g_b1hi[o * 256 + 128 + k] = h;
    g_b1lo[o * 256 + 128 + k] = __float2bfloat16_rn(v - __bfloat162float(h));
    v = w2r[i]; h = __float2bfloat16_rn(v);
    g_b2hi[o * 256 + k] = h;
    g_b2lo[o * 256 + k] = __float2bfloat16_rn(v - __bfloat162float(h));
    v = w2o[i]; h = __float2bfloat16_rn(v);
    g_b2hi[o * 256 + 128 + k] = h;
    g_b2lo[o * 256 + 128 + k] = __float2bfloat16_rn(v - __bfloat162float(h));
}

// ---------------- embedding with max_norm=1 (dual write fp32 + bf16) --------
__global__ void embed_kernel(const int* __restrict__ x,
                             const float* __restrict__ emb_w) {
    int warp = (blockIdx.x * blockDim.x + threadIdx.x) >> 5;
    int lane = threadIdx.x & 31;
    if (warp >= N_NODES) return;
    int idx = x[warp];
    const float4* row = (const float4*)(emb_w + (size_t)idx * HIDDEN);
    float4 v = __ldg(&row[lane]);
    float ss = v.x*v.x + v.y*v.y + v.z*v.z + v.w*v.w;
    ss = warp_sum(ss);
    float scale = fminf(1.0f, 1.0f / (sqrtf(ss) + 1e-7f));
    float4 o = make_float4(v.x*scale, v.y*scale, v.z*scale, v.w*scale);
    ((float4*)(g_feat0 + (size_t)warp * HIDDEN))[lane] = o;
    *(uint2*)(g_hb + (size_t)warp * 64 + lane * 2) =
        make_uint2(packbf(o.x, o.y), packbf(o.z, o.w));
}

// ---------------- zero deg / pool / cnt --------------------------------------
__global__ void zero_misc_kernel() {
    int i = blockIdx.x * blockDim.x + threadIdx.x;
    if (i < N_NODES) g_deg[i] = 0;
    if (i < N_GRAPHS * HIDDEN) g_pool[i] = 0.f;
    if (i < N_GRAPHS) g_cnt[i] = 0.f;
}

// ---------------- CSR build ---------------------------------------------------
__global__ void hist_kernel(const int* __restrict__ eidx) {
    int e = blockIdx.x * blockDim.x + threadIdx.x;
    if (e < N_EDGES) atomicAdd(&g_deg[eidx[N_EDGES + e]], 1);
}

#define SCCH 512
#define SCB  ((N_NODES + SCCH - 1) / SCCH)   // 196
__global__ void scanA_kernel() {
    __shared__ int s[256];
    int b = blockIdx.x, t = threadIdx.x;
    int base = b * SCCH;
    int v = 0;
    #pragma unroll
    for (int i = 0; i < 2; i++) {
        int j = base + t + i * 256;
        if (j < N_NODES) v += g_deg[j];
    }
    s[t] = v;
    __syncthreads();
    #pragma unroll
    for (int off = 128; off > 0; off >>= 1) {
        if (t < off) s[t] += s[t + off];
        __syncthreads();
    }
    if (t == 0) g_bsum[b] = s[0];
}
__global__ void scanB_kernel() {
    __shared__ int s[256];
    int t = threadIdx.x;
    int v = (t < SCB) ? g_bsum[t] : 0;
    s[t] = v;
    __syncthreads();
    #pragma unroll
    for (int off = 1; off < 256; off <<= 1) {
        int u = (t >= off) ? s[t - off] : 0;
        __syncthreads();
        s[t] += u;
        __syncthreads();
    }
    if (t < SCB) g_boff[t] = s[t] - v;            // exclusive
    if (t == 255) g_rowstart[N_NODES] = s[255];   // total
}
__global__ void scanC_kernel() {
    __shared__ int s[256];
    int b = blockIdx.x, t = threadIdx.x;
    int n0 = b * SCCH + 2 * t;
    int n1 = n0 + 1;
    int d0 = (n0 < N_NODES) ? g_deg[n0] : 0;
    int d1 = (n1 < N_NODES) ? g_deg[n1] : 0;
    int pair = d0 + d1;
    s[t] = pair;
    __syncthreads();
    #pragma unroll
    for (int off = 1; off < 256; off <<= 1) {
        int u = (t >= off) ? s[t - off] : 0;
        __syncthreads();
        s[t] += u;
        __syncthreads();
    }
    int off0 = g_boff[b] + s[t] - pair;
    if (n0 < N_NODES) { g_rowstart[n0] = off0;      g_cursor[n0] = off0; }
    if (n1 < N_NODES) { g_rowstart[n1] = off0 + d0; g_cursor[n1] = off0 + d0; }
}

__global__ void reorder_kernel(const int* __restrict__ eidx,
                               const float* __restrict__ ew) {
    int e = blockIdx.x * blockDim.x + threadIdx.x;
    if (e >= N_EDGES) return;
    int dst = eidx[N_EDGES + e];
    int pos = atomicAdd(&g_cursor[dst], 1);
    g_csr[pos] = make_int2(eidx[e], __float_as_int(ew[e]));
}

// ---------------- CSR aggregation, bf16 gather, warp per node ---------------
__global__ void __launch_bounds__(256)
agg_csr_kernel() {
    int warp = (blockIdx.x * blockDim.x + threadIdx.x) >> 5;
    int lane = threadIdx.x & 31;
    if (warp >= N_NODES) return;
    int s0 = g_rowstart[warp], s1 = g_rowstart[warp + 1];
    float4 acc = make_float4(0.f, 0.f, 0.f, 0.f);

    for (int base = s0; base < s1; base += 32) {
        int m = min(32, s1 - base);
        int2 e = make_int2(0, 0);
        if (base + lane < s1) e = __ldg(&g_csr[base + lane]);

        int i = 0;
        for (; i + 3 < m; i += 4) {
            int   sA = __shfl_sync(0xffffffffu, e.x, i);
            float wA = __int_as_float(__shfl_sync(0xffffffffu, e.y, i));
            int   sB = __shfl_sync(0xffffffffu, e.x, i + 1);
            float wB = __int_as_float(__shfl_sync(0xffffffffu, e.y, i + 1));
            int   sC = __shfl_sync(0xffffffffu, e.x, i + 2);
            float wC = __int_as_float(__shfl_sync(0xffffffffu, e.y, i + 2));
            int   sD = __shfl_sync(0xffffffffu, e.x, i + 3);
            float wD = __int_as_float(__shfl_sync(0xffffffffu, e.y, i + 3));
            uint2 uA = __ldg((const uint2*)(g_hb + (size_t)sA * 64) + lane);
            uint2 uB = __ldg((const uint2*)(g_hb + (size_t)sB * 64) + lane);
            uint2 uC = __ldg((const uint2*)(g_hb + (size_t)sC * 64) + lane);
            uint2 uD = __ldg((const uint2*)(g_hb + (size_t)sD * 64) + lane);
            accum_bf(acc, uA, wA);
            accum_bf(acc, uB, wB);
            accum_bf(acc, uC, wC);
            accum_bf(acc, uD, wD);
        }
        for (; i < m; i++) {
            int   se = __shfl_sync(0xffffffffu, e.x, i);
            float we = __int_as_float(__shfl_sync(0xffffffffu, e.y, i));
            uint2 ue = __ldg((const uint2*)(g_hb + (size_t)se * 64) + lane);
            accum_bf(acc, ue, we);
        }
    }
    __stcs(((float4*)(g_agg + (size_t)warp * HIDDEN)) + lane, acc);
}

// ---------------- bf16 split (3-pass) tensor-core dual GEMM ------------------
#define SB_COL_BF16   264
#define SB_PLANE_BF16 (64 * SB_COL_BF16)
#define SA_ROW_W      9
#define SA_PLANE_W    (128 * SA_ROW_W)
#define SA_BUF_W      (2 * SA_PLANE_W)
#define GEMM_SMEM_BYTES (2 * SB_PLANE_BF16 * 2 + 2 * SA_BUF_W * 4)

__global__ void __launch_bounds__(256, 2)
linear_bf16_kernel(const float* __restrict__ agg,
                   const float* __restrict__ hin,
                   const __nv_bfloat16* __restrict__ bhi,
                   const __nv_bfloat16* __restrict__ blo,
                   const float* __restrict__ bias,
                   float* __restrict__ out) {
    extern __shared__ char smem_raw[];
    __nv_bfloat16* sBhi = (__nv_bfloat16*)smem_raw;
    __nv_bfloat16* sBlo = sBhi + SB_PLANE_BF16;
    unsigned* sA = (unsigned*)(smem_raw + 2 * SB_PLANE_BF16 * 2);

    int tid = threadIdx.x, lane = tid & 31, warp = tid >> 5;
    int warpM = warp & 3, warpN = warp >> 2;
    int tileM = blockIdx.x >> 1;
    int nb = (blockIdx.x & 1) * 64;
    int rowBase = tileM * 128;

    const float4* srcHi = (const float4*)(bhi + (size_t)nb * 256);
    const float4* srcLo = (const float4*)(blo + (size_t)nb * 256);
    #pragma unroll
    for (int it = 0; it < 8; it++) {
        int idx = it * 256 + tid;
        int col = idx >> 5, q = idx & 31;
        float4 v = __ldg(srcHi + col * 32 + q);
        *(float4*)((char*)sBhi + col * (SB_COL_BF16 * 2) + q * 16) = v;
        float4 w = __ldg(srcLo + col * 32 + q);
        *(float4*)((char*)sBlo + col * (SB_COL_BF16 * 2) + q * 16) = w;
    }

    float4 cur[2], pre[2];
    auto loadA = [&](int s, float4* dst) {
        const float* src = (s * 16 < 128) ? agg : hin;
        int koff = (s * 16) & 127;
        #pragma unroll
        for (int i = 0; i < 2; i++) {
            int r = (tid >> 2) + i * 64, q = tid & 3;
            int node = rowBase + r;
            dst[i] = make_float4(0.f, 0.f, 0.f, 0.f);
            if (node < N_NODES)
                dst[i] = __ldg((const float4*)(src + (size_t)node * 128 + koff) + q);
        }
    };
    auto storeA = [&](int buf, const float4* v4) {
        unsigned* hi = sA + buf * SA_BUF_W;
        unsigned* lo = hi + SA_PLANE_W;
        #pragma unroll
        for (int i = 0; i < 2; i++) {
            int r = (tid >> 2) + i * 64, q = tid & 3;
            float4 v = v4[i];
            float hx = __bfloat162float(__float2bfloat16_rn(v.x));
            float hy = __bfloat162float(__float2bfloat16_rn(v.y));
            float hz = __bfloat162float(__float2bfloat16_rn(v.z));
            float hw = __bfloat162float(__float2bfloat16_rn(v.w));
            hi[r * SA_ROW_W + q * 2]     = packbf(v.x, v.y);
            hi[r * SA_ROW_W + q * 2 + 1] = packbf(v.z, v.w);
            lo[r * SA_ROW_W + q * 2]     = packbf(v.x - hx, v.y - hy);
            lo[r * SA_ROW_W + q * 2 + 1] = packbf(v.z - hz, v.w - hw);
        }
    };

    loadA(0, cur);
    storeA(0, cur);
    __syncthreads();

    float4 acc[2][4];
    #pragma unroll
    for (int mt = 0; mt < 2; mt++)
        #pragma unroll
        for (int j = 0; j < 4; j++)
            acc[mt][j] = make_float4(0.f, 0.f, 0.f, 0.f);

    const unsigned* Bh32 = (const unsigned*)sBhi;
    const unsigned* Bl32 = (const unsigned*)sBlo;

    for (int s = 0; s < 16; s++) {
        if (s < 15) loadA(s + 1, pre);

        const unsigned* Ahi = sA + (s & 1) * SA_BUF_W;
        const unsigned* Alo = Ahi + SA_PLANE_W;

        unsigned ah[2][4], al[2][4];
        #pragma unroll
        for (int mt = 0; mt < 2; mt++) {
            int r0 = warpM * 32 + mt * 16 + (lane >> 2);
            int w0 = lane & 3;
            ah[mt][0] = Ahi[r0 * SA_ROW_W + w0];
            ah[mt][1] = Ahi[(r0 + 8) * SA_ROW_W + w0];
            ah[mt][2] = Ahi[r0 * SA_ROW_W + w0 + 4];
            ah[mt][3] = Ahi[(r0 + 8) * SA_ROW_W + w0 + 4];
            al[mt][0] = Alo[r0 * SA_ROW_W + w0];
            al[mt][1] = Alo[(r0 + 8) * SA_ROW_W + w0];
            al[mt][2] = Alo[r0 * SA_ROW_W + w0 + 4];
            al[mt][3] = Alo[(r0 + 8) * SA_ROW_W + w0 + 4];
        }
        unsigned bh[4][2], bl[4][2];
        #pragma unroll
        for (int j = 0; j < 4; j++) {
            int c = warpN * 32 + j * 8 + (lane >> 2);
            int w = c * (SB_COL_BF16 / 2) + s * 8 + (lane & 3);
            bh[j][0] = Bh32[w];
            bh[j][1] = Bh32[w + 4];
            bl[j][0] = Bl32[w];
            bl[j][1] = Bl32[w + 4];
        }
        #pragma unroll
        for (int mt = 0; mt < 2; mt++)
            #pragma unroll
            for (int j = 0; j < 4; j++) {
                mma_bf16(acc[mt][j], al[mt], bh[j][0], bh[j][1]);
                mma_bf16(acc[mt][j], ah[mt], bl[j][0], bl[j][1]);
                mma_bf16(acc[mt][j], ah[mt], bh[j][0], bh[j][1]);
            }

        if (s < 15) storeA((s + 1) & 1, pre);
        __syncthreads();
    }

    // ---- epilogue: bias + relu + dual store (fp32 + bf16) ----
    #pragma unroll
    for (int mt = 0; mt < 2; mt++) {
        #pragma unroll
        for (int j = 0; j < 4; j++) {
            int col = nb + warpN * 32 + j * 8 + (lane & 3) * 2;
            float b0 = __ldg(bias + col);
            float b1 = __ldg(bias + col + 1);
            int row0 = rowBase + warpM * 32 + mt * 16 + (lane >> 2);
            int row1 = row0 + 8;
            float4 c = acc[mt][j];
            if (row0 < N_NODES) {
                float2 v;
                v.x = fmaxf(c.x + b0, 0.f);
                v.y = fmaxf(c.y + b1, 0.f);
                *(float2*)(out + (size_t)row0 * 128 + col) = v;
                g_hb[(size_t)row0 * 64 + (col >> 1)] = packbf(v.x, v.y);
            }
            if (row1 < N_NODES) {
                float2 v;
                v.x = fmaxf(c.z + b0, 0.f);
                v.y = fmaxf(c.w + b1, 0.f);
                *(float2*)(out + (size_t)row1 * 128 + col) = v;
                g_hb[(size_t)row1 * 64 + (col >> 1)] = packbf(v.x, v.y);
            }
        }
    }
}

// ---------------- segmented mean-pool (batch is sorted) ---------------------
#define POOL_CHUNK 256
__global__ void pool_kernel(const int* __restrict__ batch,
                            const float* __restrict__ h) {
    int n0 = blockIdx.x * POOL_CHUNK;
    int n1 = min(n0 + POOL_CHUNK, N_NODES);
    if (n0 >= N_NODES) return;
    int d = threadIdx.x;
    float acc = 0.f, cnt = 0.f;
    int cur = batch[n0];
    for (int n = n0; n < n1; n++) {
        int b = batch[n];
        if (b != cur) {
            atomicAdd(&g_pool[cur * HIDDEN + d], acc);
            if (d == 0) atomicAdd(&g_cnt[cur], cnt);
            acc = 0.f; cnt = 0.f; cur = b;
        }
        acc += h[(size_t)n * HIDDEN + d];
        cnt += 1.f;
    }
    atomicAdd(&g_pool[cur * HIDDEN + d], acc);
    if (d == 0) atomicAdd(&g_cnt[cur], cnt);
}

// ---------------- classifier -------------------------------------------------
__global__ void __launch_bounds__(256)
classifier_kernel(const float* __restrict__ cls1_w,
                  const float* __restrict__ cls1_b,
                  const float* __restrict__ cls2_w,
                  const float* __restrict__ cls2_b,
                  float* __restrict__ out) {
    __shared__ float s_w1[L1DIM * HIDDEN];
    __shared__ float s_b1[L1DIM];
    __shared__ float s_w2[2 * L1DIM];
    __shared__ float s_b2[2];

    for (int i = threadIdx.x; i < L1DIM * HIDDEN; i += blockDim.x)
        s_w1[i] = cls1_w[i];
    if (threadIdx.x < L1DIM) s_b1[threadIdx.x] = cls1_b[threadIdx.x];
    if (threadIdx.x < 2 * L1DIM) s_w2[threadIdx.x] = cls2_w[threadIdx.x];
    if (threadIdx.x < 2) s_b2[threadIdx.x] = cls2_b[threadIdx.x];
    __syncthreads();

    int g = blockIdx.x * 8 + (threadIdx.x >> 5);
    int lane = threadIdx.x & 31;
    if (g >= N_GRAPHS) return;

    float c = fmaxf(g_cnt[g], 1.0f);
    float4 p = ((const float4*)(g_pool + g * HIDDEN))[lane];
    float inv = 1.0f / c;
    p.x *= inv; p.y *= inv; p.z *= inv; p.w *= inv;

    float z1a = 0.f, z1b = 0.f;
    const float4* w14 = (const float4*)s_w1;
    #pragma unroll 4
    for (int j = 0; j < L1DIM; j++) {
        float4 w = w14[j * 32 + lane];
        float s = p.x*w.x + p.y*w.y + p.z*w.z + p.w*w.w;
        s = warp_sum(s);
        float v = fmaxf(s + s_b1[j], 0.f);
        if (j < 32) { if (lane == j)      z1a = v; }
        else        { if (lane == j - 32) z1b = v; }
    }
    float t0 = s_w2[lane] * z1a + s_w2[lane + 32] * z1b;
    float t1 = s_w2[L1DIM + lane] * z1a + s_w2[L1DIM + lane + 32] * z1b;
    t0 = warp_sum(t0);
    t1 = warp_sum(t1);
    if (lane == 0) {
        float z0 = t0 + s_b2[0];
        float z1 = t1 + s_b2[1];
        float m = fmaxf(z0, z1);
        float e0 = expf(z0 - m), e1 = expf(z1 - m);
        float d = e0 + e1;
        out[g * 2 + 0] = e0 / d;
        out[g * 2 + 1] = e1 / d;
    }
}

// ---------------- launch ----------------------------------------------------
extern "C" void kernel_launch(void* const* d_in, const int* in_sizes, int n_in,
                              void* d_out, int out_size) {
    const int*   x       = (const int*)  d_in[0];
    const int*   eidx    = (const int*)  d_in[1];
    const float* eweight = (const float*)d_in[2];
    const int*   batch   = (const int*)  d_in[3];
    const float* emb_w   = (const float*)d_in[4];
    const float* w1_rel  = (const float*)d_in[5];
    const float* b1_rel  = (const float*)d_in[6];
    const float* w1_root = (const float*)d_in[7];
    const float* w2_rel  = (const float*)d_in[8];
    const float* b2_rel  = (const float*)d_in[9];
    const float* w2_root = (const float*)d_in[10];
    const float* cls1_w  = (const float*)d_in[11];
    const float* cls1_b  = (const float*)d_in[12];
    const float* cls2_w  = (const float*)d_in[13];
    const float* cls2_b  = (const float*)d_in[14];
    float* out = (float*)d_out;

    float *p_f0, *p_f1, *p_agg;
    __nv_bfloat16 *p_b1hi, *p_b1lo, *p_b2hi, *p_b2lo;
    cudaGetSymbolAddress((void**)&p_f0,   g_feat0);
    cudaGetSymbolAddress((void**)&p_f1,   g_feat1);
    cudaGetSymbolAddress((void**)&p_agg,  g_agg);
    cudaGetSymbolAddress((void**)&p_b1hi, g_b1hi);
    cudaGetSymbolAddress((void**)&p_b1lo, g_b1lo);
    cudaGetSymbolAddress((void**)&p_b2hi, g_b2hi);
    cudaGetSymbolAddress((void**)&p_b2lo, g_b2lo);

    static int smem_set = 0;
    if (!smem_set) {
        cudaFuncSetAttribute(linear_bf16_kernel,
                             cudaFuncAttributeMaxDynamicSharedMemorySize,
                             GEMM_SMEM_BYTES);
        smem_set = 1;
    }

    prep_weights_kernel<<<64, 256>>>(w1_rel, w1_root, w2_rel, w2_root);
    zero_misc_kernel<<<(N_NODES + 255) / 256, 256>>>();
    embed_kernel<<<(N_NODES + 7) / 8, 256>>>(x, emb_w);

    // CSR build (shared by both layers)
    hist_kernel<<<(N_EDGES + 255) / 256, 256>>>(eidx);
    scanA_kernel<<<SCB, 256>>>();
    scanB_kernel<<<1, 256>>>();
    scanC_kernel<<<SCB, 256>>>();
    reorder_kernel<<<(N_EDGES + 255) / 256, 256>>>(eidx, eweight);

    int nTiles = (N_NODES + 127) / 128;
    // layer 1
    agg_csr_kernel<<<(N_NODES * 32 + 255) / 256, 256>>>();
    linear_bf16_kernel<<<nTiles * 2, 256, GEMM_SMEM_BYTES>>>(
        p_agg, p_f0, p_b1hi, p_b1lo, b1_rel, p_f1);
    // layer 2
    agg_csr_kernel<<<(N_NODES * 32 + 255) / 256, 256>>>();
    linear_bf16_kernel<<<nTiles * 2, 256, GEMM_SMEM_BYTES>>>(
        p_agg, p_f1, p_b2hi, p_b2lo, b2_rel, p_f0);

    // pool + classify
    pool_kernel<<<(N_NODES + POOL_CHUNK - 1) / POOL_CHUNK, HIDDEN>>>(batch, p_f0);
    classifier_kernel<<<32, 256>>>(cls1_w, cls1_b, cls2_w, cls2_b, out);
}

// round 8
// speedup vs baseline: 3.0188x; 1.2932x over previous
#include <cuda_runtime.h>
#include <cuda_bf16.h>
#include <math.h>

#define N_NODES  100000
#define N_EDGES  1600000
#define HIDDEN   128
#define N_GRAPHS 256
#define L1DIM    64

// ---------------- scratch (device globals; no allocations allowed) ----------
__device__ float g_feat0[N_NODES * HIDDEN];            // layer-2 out (fp32, pool)
__device__ float g_pool [N_GRAPHS * HIDDEN];
__device__ float g_cnt  [N_GRAPHS];
// packed bf16x2 node features (gather table + GEMM A root half), 25.6 MB
__device__ __align__(16) unsigned g_hb  [N_NODES * 64];
// packed bf16x2 aggregation output (GEMM A rel half), 25.6 MB
__device__ __align__(16) unsigned g_aggb[N_NODES * 64];
// CSR scratch
__device__ int   g_deg     [N_NODES];
__device__ int   g_rowstart[N_NODES + 1];
__device__ int   g_cursor  [N_NODES];
__device__ int   g_bsum    [256];
__device__ int   g_boff    [256];
__device__ __align__(16) int2 g_csr[N_EDGES];
// pre-split weights: [o 0..127][k 0..255] (k<128 = rel, k>=128 = root)
__device__ __align__(16) __nv_bfloat16 g_b1hi[HIDDEN * 256];
__device__ __align__(16) __nv_bfloat16 g_b1lo[HIDDEN * 256];
__device__ __align__(16) __nv_bfloat16 g_b2hi[HIDDEN * 256];
__device__ __align__(16) __nv_bfloat16 g_b2lo[HIDDEN * 256];

// ---------------- helpers ----------------------------------------------------
__device__ __forceinline__ float warp_sum(float v) {
    #pragma unroll
    for (int m = 16; m > 0; m >>= 1) v += __shfl_xor_sync(0xffffffffu, v, m);
    return v;
}
__device__ __forceinline__ unsigned packbf(float a, float b) {
    __nv_bfloat162 t = __floats2bfloat162_rn(a, b);   // low = a (even dim)
    return *reinterpret_cast<unsigned*>(&t);
}
__device__ __forceinline__ void accum_bf(float4& acc, uint2 u, float w) {
    float2 f0 = __bfloat1622float2(*reinterpret_cast<__nv_bfloat162*>(&u.x));
    float2 f1 = __bfloat1622float2(*reinterpret_cast<__nv_bfloat162*>(&u.y));
    acc.x += f0.x * w;
    acc.y += f0.y * w;
    acc.z += f1.x * w;
    acc.w += f1.y * w;
}
__device__ __forceinline__ void mma_bf16(float4& c, const unsigned* a,
                                         unsigned b0, unsigned b1) {
    asm volatile(
        "mma.sync.aligned.m16n8k16.row.col.f32.bf16.bf16.f32 "
        "{%0,%1,%2,%3}, {%4,%5,%6,%7}, {%8,%9}, {%0,%1,%2,%3};\n"
        : "+f"(c.x), "+f"(c.y), "+f"(c.z), "+f"(c.w)
        : "r"(a[0]), "r"(a[1]), "r"(a[2]), "r"(a[3]), "r"(b0), "r"(b1));
}

// ---------------- weight prep: split f32 -> bf16 hi/lo, pack [o][k] ---------
__global__ void prep_weights_kernel(const float* __restrict__ w1r,
                                    const float* __restrict__ w1o,
                                    const float* __restrict__ w2r,
                                    const float* __restrict__ w2o) {
    int i = blockIdx.x * blockDim.x + threadIdx.x;
    if (i >= HIDDEN * HIDDEN) return;
    int o = i >> 7, k = i & 127;
    float v;
    __nv_bfloat16 h;
    v = w1r[i]; h = __float2bfloat16_rn(v);
    g_b1hi[o * 256 + k] = h;
    g_b1lo[o * 256 + k] = __float2bfloat16_rn(v - __bfloat162float(h));
    v = w1o[i]; h = __float2bfloat16_rn(v);
    g_b1hi[o * 256 + 128 + k] = h;
    g_b1lo[o * 256 + 128 + k] = __float2bfloat16_rn(v - __bfloat162float(h));
    v = w2r[i]; h = __float2bfloat16_rn(v);
    g_b2hi[o * 256 + k] = h;
    g_b2lo[o * 256 + k] = __float2bfloat16_rn(v - __bfloat162float(h));
    v = w2o[i]; h = __float2bfloat16_rn(v);
    g_b2hi[o * 256 + 128 + k] = h;
    g_b2lo[o * 256 + 128 + k] = __float2bfloat16_rn(v - __bfloat162float(h));
}

// ---------------- embedding with max_norm=1 (bf16 table only) ---------------
__global__ void embed_kernel(const int* __restrict__ x,
                             const float* __restrict__ emb_w) {
    int warp = (blockIdx.x * blockDim.x + threadIdx.x) >> 5;
    int lane = threadIdx.x & 31;
    if (warp >= N_NODES) return;
    int idx = x[warp];
    const float4* row = (const float4*)(emb_w + (size_t)idx * HIDDEN);
    float4 v = __ldg(&row[lane]);
    float ss = v.x*v.x + v.y*v.y + v.z*v.z + v.w*v.w;
    ss = warp_sum(ss);
    float scale = fminf(1.0f, 1.0f / (sqrtf(ss) + 1e-7f));
    float4 o = make_float4(v.x*scale, v.y*scale, v.z*scale, v.w*scale);
    *(uint2*)(g_hb + (size_t)warp * 64 + lane * 2) =
        make_uint2(packbf(o.x, o.y), packbf(o.z, o.w));
}

// ---------------- zero deg / pool / cnt --------------------------------------
__global__ void zero_misc_kernel() {
    int i = blockIdx.x * blockDim.x + threadIdx.x;
    if (i < N_NODES) g_deg[i] = 0;
    if (i < N_GRAPHS * HIDDEN) g_pool[i] = 0.f;
    if (i < N_GRAPHS) g_cnt[i] = 0.f;
}

// ---------------- CSR build ---------------------------------------------------
__global__ void hist_kernel(const int* __restrict__ eidx) {
    int e4 = blockIdx.x * blockDim.x + threadIdx.x;
    if (e4 >= N_EDGES / 4) return;
    int4 d = __ldg((const int4*)(eidx + N_EDGES) + e4);
    atomicAdd(&g_deg[d.x], 1);
    atomicAdd(&g_deg[d.y], 1);
    atomicAdd(&g_deg[d.z], 1);
    atomicAdd(&g_deg[d.w], 1);
}

#define SCCH 512
#define SCB  ((N_NODES + SCCH - 1) / SCCH)   // 196
__global__ void scanA_kernel() {
    __shared__ int s[256];
    int b = blockIdx.x, t = threadIdx.x;
    int base = b * SCCH;
    int v = 0;
    #pragma unroll
    for (int i = 0; i < 2; i++) {
        int j = base + t + i * 256;
        if (j < N_NODES) v += g_deg[j];
    }
    s[t] = v;
    __syncthreads();
    #pragma unroll
    for (int off = 128; off > 0; off >>= 1) {
        if (t < off) s[t] += s[t + off];
        __syncthreads();
    }
    if (t == 0) g_bsum[b] = s[0];
}
__global__ void scanB_kernel() {
    __shared__ int s[256];
    int t = threadIdx.x;
    int v = (t < SCB) ? g_bsum[t] : 0;
    s[t] = v;
    __syncthreads();
    #pragma unroll
    for (int off = 1; off < 256; off <<= 1) {
        int u = (t >= off) ? s[t - off] : 0;
        __syncthreads();
        s[t] += u;
        __syncthreads();
    }
    if (t < SCB) g_boff[t] = s[t] - v;            // exclusive
    if (t == 255) g_rowstart[N_NODES] = s[255];   // total
}
__global__ void scanC_kernel() {
    __shared__ int s[256];
    int b = blockIdx.x, t = threadIdx.x;
    int n0 = b * SCCH + 2 * t;
    int n1 = n0 + 1;
    int d0 = (n0 < N_NODES) ? g_deg[n0] : 0;
    int d1 = (n1 < N_NODES) ? g_deg[n1] : 0;
    int pair = d0 + d1;
    s[t] = pair;
    __syncthreads();
    #pragma unroll
    for (int off = 1; off < 256; off <<= 1) {
        int u = (t >= off) ? s[t - off] : 0;
        __syncthreads();
        s[t] += u;
        __syncthreads();
    }
    int off0 = g_boff[b] + s[t] - pair;
    if (n0 < N_NODES) { g_rowstart[n0] = off0;      g_cursor[n0] = off0; }
    if (n1 < N_NODES) { g_rowstart[n1] = off0 + d0; g_cursor[n1] = off0 + d0; }
}

__global__ void reorder_kernel(const int* __restrict__ eidx,
                               const float* __restrict__ ew) {
    int e4 = blockIdx.x * blockDim.x + threadIdx.x;
    if (e4 >= N_EDGES / 4) return;
    int4   s4 = __ldg((const int4*)eidx + e4);
    int4   d4 = __ldg((const int4*)(eidx + N_EDGES) + e4);
    float4 w4 = __ldg((const float4*)ew + e4);
    int p;
    p = atomicAdd(&g_cursor[d4.x], 1); g_csr[p] = make_int2(s4.x, __float_as_int(w4.x));
    p = atomicAdd(&g_cursor[d4.y], 1); g_csr[p] = make_int2(s4.y, __float_as_int(w4.y));
    p = atomicAdd(&g_cursor[d4.z], 1); g_csr[p] = make_int2(s4.z, __float_as_int(w4.z));
    p = atomicAdd(&g_cursor[d4.w], 1); g_csr[p] = make_int2(s4.w, __float_as_int(w4.w));
}

// ---------------- CSR aggregation, bf16 gather, warp per node ---------------
// writes agg as packed bf16x2 (fp32 accumulation internally)
__global__ void __launch_bounds__(256)
agg_csr_kernel() {
    int warp = (blockIdx.x * blockDim.x + threadIdx.x) >> 5;
    int lane = threadIdx.x & 31;
    if (warp >= N_NODES) return;
    int s0 = g_rowstart[warp], s1 = g_rowstart[warp + 1];
    float4 acc = make_float4(0.f, 0.f, 0.f, 0.f);

    for (int base = s0; base < s1; base += 32) {
        int m = min(32, s1 - base);
        int2 e = make_int2(0, 0);
        if (base + lane < s1) e = __ldg(&g_csr[base + lane]);

        int i = 0;
        for (; i + 3 < m; i += 4) {
            int   sA = __shfl_sync(0xffffffffu, e.x, i);
            float wA = __int_as_float(__shfl_sync(0xffffffffu, e.y, i));
            int   sB = __shfl_sync(0xffffffffu, e.x, i + 1);
            float wB = __int_as_float(__shfl_sync(0xffffffffu, e.y, i + 1));
            int   sC = __shfl_sync(0xffffffffu, e.x, i + 2);
            float wC = __int_as_float(__shfl_sync(0xffffffffu, e.y, i + 2));
            int   sD = __shfl_sync(0xffffffffu, e.x, i + 3);
            float wD = __int_as_float(__shfl_sync(0xffffffffu, e.y, i + 3));
            uint2 uA = __ldg((const uint2*)(g_hb + (size_t)sA * 64) + lane);
            uint2 uB = __ldg((const uint2*)(g_hb + (size_t)sB * 64) + lane);
            uint2 uC = __ldg((const uint2*)(g_hb + (size_t)sC * 64) + lane);
            uint2 uD = __ldg((const uint2*)(g_hb + (size_t)sD * 64) + lane);
            accum_bf(acc, uA, wA);
            accum_bf(acc, uB, wB);
            accum_bf(acc, uC, wC);
            accum_bf(acc, uD, wD);
        }
        for (; i < m; i++) {
            int   se = __shfl_sync(0xffffffffu, e.x, i);
            float we = __int_as_float(__shfl_sync(0xffffffffu, e.y, i));
            uint2 ue = __ldg((const uint2*)(g_hb + (size_t)se * 64) + lane);
            accum_bf(acc, ue, we);
        }
    }
    uint2 outp = make_uint2(packbf(acc.x, acc.y), packbf(acc.z, acc.w));
    __stcs((uint2*)(g_aggb + (size_t)warp * 64) + lane, outp);
}

// ---------------- 2-pass bf16 tensor-core dual GEMM --------------------------
// out = relu([aggb | hb](100k x 256, bf16) @ (Bhi + Blo)(256 x 128) + bias)
// Block: 128 rows x 64 cols; 8 warps = 4(M) x 2(N); warp tile 32x32.
#define SB_COL_BF16   264                      // 256 k + 8 pad (bf16 elems)
#define SB_PLANE_BF16 (64 * SB_COL_BF16)
#define SA_ROW_W      12                       // 8 data words + 4 pad
#define SA_PLANE_W    (128 * SA_ROW_W)         // 1536 words
#define GEMM_SMEM_BYTES (2 * SB_PLANE_BF16 * 2 + 2 * SA_PLANE_W * 4)  // 79872

__global__ void __launch_bounds__(256, 2)
linear_bf16_kernel(const unsigned* __restrict__ aggb,
                   const unsigned* __restrict__ hb,
                   const __nv_bfloat16* __restrict__ bhi,
                   const __nv_bfloat16* __restrict__ blo,
                   const float* __restrict__ bias,
                   float* __restrict__ outF,        // fp32 out (may be null)
                   unsigned* __restrict__ outB) {   // bf16 packed out (may be null)
    extern __shared__ char smem_raw[];
    __nv_bfloat16* sBhi = (__nv_bfloat16*)smem_raw;
    __nv_bfloat16* sBlo = sBhi + SB_PLANE_BF16;
    unsigned* sA = (unsigned*)(smem_raw + 2 * SB_PLANE_BF16 * 2);

    int tid = threadIdx.x, lane = tid & 31, warp = tid >> 5;
    int warpM = warp & 3, warpN = warp >> 2;
    int tileM = blockIdx.x >> 1;
    int nb = (blockIdx.x & 1) * 64;
    int rowBase = tileM * 128;

    // ---- load B 64-col slice (hi+lo) into smem ----
    const float4* srcHi = (const float4*)(bhi + (size_t)nb * 256);
    const float4* srcLo = (const float4*)(blo + (size_t)nb * 256);
    #pragma unroll
    for (int it = 0; it < 8; it++) {
        int idx = it * 256 + tid;
        int col = idx >> 5, q = idx & 31;
        float4 v = __ldg(srcHi + col * 32 + q);
        *(float4*)((char*)sBhi + col * (SB_COL_BF16 * 2) + q * 16) = v;
        float4 w = __ldg(srcLo + col * 32 + q);
        *(float4*)((char*)sBlo + col * (SB_COL_BF16 * 2) + q * 16) = w;
    }

    // ---- A stage loader: stage s covers k = s*16 .. s*16+15 (8 words/row) --
    int rA = tid >> 1, qA = tid & 1;          // row 0..127, quad 0..1
    uint4 cur, pre;
    auto loadA = [&](int s, uint4& dst) {
        const unsigned* src = (s < 8) ? aggb : hb;
        int woff = (s & 7) * 8 + qA * 4;
        int node = rowBase + rA;
        dst = make_uint4(0u, 0u, 0u, 0u);
        if (node < N_NODES)
            dst = __ldg((const uint4*)(src + (size_t)node * 64 + woff));
    };
    auto storeA = [&](int buf, const uint4& v) {
        *(uint4*)(sA + buf * SA_PLANE_W + rA * SA_ROW_W + qA * 4) = v;
    };

    loadA(0, cur);
    storeA(0, cur);
    __syncthreads();

    float4 acc[2][4];
    #pragma unroll
    for (int mt = 0; mt < 2; mt++)
        #pragma unroll
        for (int j = 0; j < 4; j++)
            acc[mt][j] = make_float4(0.f, 0.f, 0.f, 0.f);

    const unsigned* Bh32 = (const unsigned*)sBhi;
    const unsigned* Bl32 = (const unsigned*)sBlo;

    for (int s = 0; s < 16; s++) {
        if (s < 15) loadA(s + 1, pre);

        const unsigned* Ab = sA + (s & 1) * SA_PLANE_W;

        unsigned ah[2][4];
        #pragma unroll
        for (int mt = 0; mt < 2; mt++) {
            int r0 = warpM * 32 + mt * 16 + (lane >> 2);
            int w0 = lane & 3;
            ah[mt][0] = Ab[r0 * SA_ROW_W + w0];
            ah[mt][1] = Ab[(r0 + 8) * SA_ROW_W + w0];
            ah[mt][2] = Ab[r0 * SA_ROW_W + w0 + 4];
            ah[mt][3] = Ab[(r0 + 8) * SA_ROW_W + w0 + 4];
        }
        unsigned bh[4][2], bl[4][2];
        #pragma unroll
        for (int j = 0; j < 4; j++) {
            int c = warpN * 32 + j * 8 + (lane >> 2);
            int w = c * (SB_COL_BF16 / 2) + s * 8 + (lane & 3);
            bh[j][0] = Bh32[w];
            bh[j][1] = Bh32[w + 4];
            bl[j][0] = Bl32[w];
            bl[j][1] = Bl32[w + 4];
        }
        #pragma unroll
        for (int mt = 0; mt < 2; mt++)
            #pragma unroll
            for (int j = 0; j < 4; j++) {
                mma_bf16(acc[mt][j], ah[mt], bh[j][0], bh[j][1]);
                mma_bf16(acc[mt][j], ah[mt], bl[j][0], bl[j][1]);
            }

        if (s < 15) storeA((s + 1) & 1, pre);
        __syncthreads();
    }

    // ---- epilogue: bias + relu + store (fp32 and/or packed bf16) ----
    #pragma unroll
    for (int mt = 0; mt < 2; mt++) {
        #pragma unroll
        for (int j = 0; j < 4; j++) {
            int col = nb + warpN * 32 + j * 8 + (lane & 3) * 2;
            float b0 = __ldg(bias + col);
            float b1 = __ldg(bias + col + 1);
            int row0 = rowBase + warpM * 32 + mt * 16 + (lane >> 2);
            int row1 = row0 + 8;
            float4 c = acc[mt][j];
            if (row0 < N_NODES) {
                float vx = fmaxf(c.x + b0, 0.f);
                float vy = fmaxf(c.y + b1, 0.f);
                if (outF) *(float2*)(outF + (size_t)row0 * 128 + col) =
                              make_float2(vx, vy);
                if (outB) outB[(size_t)row0 * 64 + (col >> 1)] = packbf(vx, vy);
            }
            if (row1 < N_NODES) {
                float vx = fmaxf(c.z + b0, 0.f);
                float vy = fmaxf(c.w + b1, 0.f);
                if (outF) *(float2*)(outF + (size_t)row1 * 128 + col) =
                              make_float2(vx, vy);
                if (outB) outB[(size_t)row1 * 64 + (col >> 1)] = packbf(vx, vy);
            }
        }
    }
}

// ---------------- segmented mean-pool (batch is sorted) ---------------------
#define POOL_CHUNK 256
__global__ void pool_kernel(const int* __restrict__ batch,
                            const float* __restrict__ h) {
    int n0 = blockIdx.x * POOL_CHUNK;
    int n1 = min(n0 + POOL_CHUNK, N_NODES);
    if (n0 >= N_NODES) return;
    int d = threadIdx.x;
    float acc = 0.f, cnt = 0.f;
    int cur = batch[n0];
    for (int n = n0; n < n1; n++) {
        int b = batch[n];
        if (b != cur) {
            atomicAdd(&g_pool[cur * HIDDEN + d], acc);
            if (d == 0) atomicAdd(&g_cnt[cur], cnt);
            acc = 0.f; cnt = 0.f; cur = b;
        }
        acc += h[(size_t)n * HIDDEN + d];
        cnt += 1.f;
    }
    atomicAdd(&g_pool[cur * HIDDEN + d], acc);
    if (d == 0) atomicAdd(&g_cnt[cur], cnt);
}

// ---------------- classifier -------------------------------------------------
__global__ void __launch_bounds__(256)
classifier_kernel(const float* __restrict__ cls1_w,
                  const float* __restrict__ cls1_b,
                  const float* __restrict__ cls2_w,
                  const float* __restrict__ cls2_b,
                  float* __restrict__ out) {
    __shared__ float s_w1[L1DIM * HIDDEN];
    __shared__ float s_b1[L1DIM];
    __shared__ float s_w2[2 * L1DIM];
    __shared__ float s_b2[2];

    for (int i = threadIdx.x; i < L1DIM * HIDDEN; i += blockDim.x)
        s_w1[i] = cls1_w[i];
    if (threadIdx.x < L1DIM) s_b1[threadIdx.x] = cls1_b[threadIdx.x];
    if (threadIdx.x < 2 * L1DIM) s_w2[threadIdx.x] = cls2_w[threadIdx.x];
    if (threadIdx.x < 2) s_b2[threadIdx.x] = cls2_b[threadIdx.x];
    __syncthreads();

    int g = blockIdx.x * 8 + (threadIdx.x >> 5);
    int lane = threadIdx.x & 31;
    if (g >= N_GRAPHS) return;

    float c = fmaxf(g_cnt[g], 1.0f);
    float4 p = ((const float4*)(g_pool + g * HIDDEN))[lane];
    float inv = 1.0f / c;
    p.x *= inv; p.y *= inv; p.z *= inv; p.w *= inv;

    float z1a = 0.f, z1b = 0.f;
    const float4* w14 = (const float4*)s_w1;
    #pragma unroll 4
    for (int j = 0; j < L1DIM; j++) {
        float4 w = w14[j * 32 + lane];
        float s = p.x*w.x + p.y*w.y + p.z*w.z + p.w*w.w;
        s = warp_sum(s);
        float v = fmaxf(s + s_b1[j], 0.f);
        if (j < 32) { if (lane == j)      z1a = v; }
        else        { if (lane == j - 32) z1b = v; }
    }
    float t0 = s_w2[lane] * z1a + s_w2[lane + 32] * z1b;
    float t1 = s_w2[L1DIM + lane] * z1a + s_w2[L1DIM + lane + 32] * z1b;
    t0 = warp_sum(t0);
    t1 = warp_sum(t1);
    if (lane == 0) {
        float z0 = t0 + s_b2[0];
        float z1 = t1 + s_b2[1];
        float m = fmaxf(z0, z1);
        float e0 = expf(z0 - m), e1 = expf(z1 - m);
        float d = e0 + e1;
        out[g * 2 + 0] = e0 / d;
        out[g * 2 + 1] = e1 / d;
    }
}

// ---------------- launch ----------------------------------------------------
extern "C" void kernel_launch(void* const* d_in, const int* in_sizes, int n_in,
                              void* d_out, int out_size) {
    const int*   x       = (const int*)  d_in[0];
    const int*   eidx    = (const int*)  d_in[1];
    const float* eweight = (const float*)d_in[2];
    const int*   batch   = (const int*)  d_in[3];
    const float* emb_w   = (const float*)d_in[4];
    const float* w1_rel  = (const float*)d_in[5];
    const float* b1_rel  = (const float*)d_in[6];
    const float* w1_root = (const float*)d_in[7];
    const float* w2_rel  = (const float*)d_in[8];
    const float* b2_rel  = (const float*)d_in[9];
    const float* w2_root = (const float*)d_in[10];
    const float* cls1_w  = (const float*)d_in[11];
    const float* cls1_b  = (const float*)d_in[12];
    const float* cls2_w  = (const float*)d_in[13];
    const float* cls2_b  = (const float*)d_in[14];
    float* out = (float*)d_out;

    float* p_f0;
    unsigned *p_hb, *p_aggb;
    __nv_bfloat16 *p_b1hi, *p_b1lo, *p_b2hi, *p_b2lo;
    cudaGetSymbolAddress((void**)&p_f0,   g_feat0);
    cudaGetSymbolAddress((void**)&p_hb,   g_hb);
    cudaGetSymbolAddress((void**)&p_aggb, g_aggb);
    cudaGetSymbolAddress((void**)&p_b1hi, g_b1hi);
    cudaGetSymbolAddress((void**)&p_b1lo, g_b1lo);
    cudaGetSymbolAddress((void**)&p_b2hi, g_b2hi);
    cudaGetSymbolAddress((void**)&p_b2lo, g_b2lo);

    static int smem_set = 0;
    if (!smem_set) {
        cudaFuncSetAttribute(linear_bf16_kernel,
                             cudaFuncAttributeMaxDynamicSharedMemorySize,
                             GEMM_SMEM_BYTES);
        smem_set = 1;
    }

    prep_weights_kernel<<<64, 256>>>(w1_rel, w1_root, w2_rel, w2_root);
    zero_misc_kernel<<<(N_NODES + 255) / 256, 256>>>();
    embed_kernel<<<(N_NODES + 7) / 8, 256>>>(x, emb_w);

    // CSR build (shared by both layers)
    hist_kernel<<<(N_EDGES / 4 + 255) / 256, 256>>>(eidx);
    scanA_kernel<<<SCB, 256>>>();
    scanB_kernel<<<1, 256>>>();
    scanC_kernel<<<SCB, 256>>>();
    reorder_kernel<<<(N_EDGES / 4 + 255) / 256, 256>>>(eidx, eweight);

    int nTiles = (N_NODES + 127) / 128;
    // layer 1: out -> g_hb only (bf16)
    agg_csr_kernel<<<(N_NODES * 32 + 255) / 256, 256>>>();
    linear_bf16_kernel<<<nTiles * 2, 256, GEMM_SMEM_BYTES>>>(
        p_aggb, p_hb, p_b1hi, p_b1lo, b1_rel, nullptr, p_hb);
    // layer 2: out -> g_feat0 (fp32, for pooling)
    agg_csr_kernel<<<(N_NODES * 32 + 255) / 256, 256>>>();
    linear_bf16_kernel<<<nTiles * 2, 256, GEMM_SMEM_BYTES>>>(
        p_aggb, p_hb, p_b2hi, p_b2lo, b2_rel, p_f0, nullptr);

    // pool + classify
    pool_kernel<<<(N_NODES + POOL_CHUNK - 1) / POOL_CHUNK, HIDDEN>>>(batch, p_f0);
    classifier_kernel<<<32, 256>>>(cls1_w, cls1_b, cls2_w, cls2_b, out);
}

// round 10
// speedup vs baseline: 3.1013x; 1.0273x over previous
#include <cuda_runtime.h>
#include <cuda_bf16.h>
#include <math.h>

#define N_NODES  100000
#define N_EDGES  1600000
#define HIDDEN   128
#define N_GRAPHS 256
#define L1DIM    64

// ---------------- scratch (device globals; no allocations allowed) ----------
__device__ float g_pool [N_GRAPHS * HIDDEN];
__device__ float g_cnt  [N_GRAPHS];
// packed bf16x2 node features (gather table + GEMM A root half), 25.6 MB
__device__ __align__(16) unsigned g_hb  [N_NODES * 64];
// packed bf16x2 aggregation output / layer-2 output, 25.6 MB
__device__ __align__(16) unsigned g_aggb[N_NODES * 64];
// CSR scratch
__device__ int   g_deg     [N_NODES];
__device__ int   g_rowstart[N_NODES + 1];
__device__ int   g_cursor  [N_NODES];
__device__ int   g_bsum    [256];
__device__ int   g_boff    [256];
__device__ __align__(16) int2 g_csr[N_EDGES];
// pre-split weights: [o 0..127][k 0..255] (k<128 = rel, k>=128 = root)
__device__ __align__(16) __nv_bfloat16 g_b1hi[HIDDEN * 256];
__device__ __align__(16) __nv_bfloat16 g_b1lo[HIDDEN * 256];
__device__ __align__(16) __nv_bfloat16 g_b2hi[HIDDEN * 256];
__device__ __align__(16) __nv_bfloat16 g_b2lo[HIDDEN * 256];

// ---------------- helpers ----------------------------------------------------
__device__ __forceinline__ float warp_sum(float v) {
    #pragma unroll
    for (int m = 16; m > 0; m >>= 1) v += __shfl_xor_sync(0xffffffffu, v, m);
    return v;
}
__device__ __forceinline__ unsigned packbf(float a, float b) {
    __nv_bfloat162 t = __floats2bfloat162_rn(a, b);   // low = a (even dim)
    return *reinterpret_cast<unsigned*>(&t);
}
__device__ __forceinline__ void accum_bf(float4& acc, uint2 u, float w) {
    float2 f0 = __bfloat1622float2(*reinterpret_cast<__nv_bfloat162*>(&u.x));
    float2 f1 = __bfloat1622float2(*reinterpret_cast<__nv_bfloat162*>(&u.y));
    acc.x += f0.x * w;
    acc.y += f0.y * w;
    acc.z += f1.x * w;
    acc.w += f1.y * w;
}
__device__ __forceinline__ void mma_bf16(float4& c, const unsigned* a,
                                         unsigned b0, unsigned b1) {
    asm volatile(
        "mma.sync.aligned.m16n8k16.row.col.f32.bf16.bf16.f32 "
        "{%0,%1,%2,%3}, {%4,%5,%6,%7}, {%8,%9}, {%0,%1,%2,%3};\n"
        : "+f"(c.x), "+f"(c.y), "+f"(c.z), "+f"(c.w)
        : "r"(a[0]), "r"(a[1]), "r"(a[2]), "r"(a[3]), "r"(b0), "r"(b1));
}

// ---------------- weight prep: split f32 -> bf16 hi/lo, pack [o][k] ---------
__global__ void prep_weights_kernel(const float* __restrict__ w1r,
                                    const float* __restrict__ w1o,
                                    const float* __restrict__ w2r,
                                    const float* __restrict__ w2o) {
    int i = blockIdx.x * blockDim.x + threadIdx.x;
    if (i >= HIDDEN * HIDDEN) return;
    int o = i >> 7, k = i & 127;
    float v;
    __nv_bfloat16 h;
    v = w1r[i]; h = __float2bfloat16_rn(v);
    g_b1hi[o * 256 + k] = h;
    g_b1lo[o * 256 + k] = __float2bfloat16_rn(v - __bfloat162float(h));
    v = w1o[i]; h = __float2bfloat16_rn(v);
    g_b1hi[o * 256 + 128 + k] = h;
    g_b1lo[o * 256 + 128 + k] = __float2bfloat16_rn(v - __bfloat162float(h));
    v = w2r[i]; h = __float2bfloat16_rn(v);
    g_b2hi[o * 256 + k] = h;
    g_b2lo[o * 256 + k] = __float2bfloat16_rn(v - __bfloat162float(h));
    v = w2o[i]; h = __float2bfloat16_rn(v);
    g_b2hi[o * 256 + 128 + k] = h;
    g_b2lo[o * 256 + 128 + k] = __float2bfloat16_rn(v - __bfloat162float(h));
}

// ---------------- embedding with max_norm=1 (bf16 table only) ---------------
__global__ void embed_kernel(const int* __restrict__ x,
                             const float* __restrict__ emb_w) {
    int warp = (blockIdx.x * blockDim.x + threadIdx.x) >> 5;
    int lane = threadIdx.x & 31;
    if (warp >= N_NODES) return;
    int idx = x[warp];
    const float4* row = (const float4*)(emb_w + (size_t)idx * HIDDEN);
    float4 v = __ldg(&row[lane]);
    float ss = v.x*v.x + v.y*v.y + v.z*v.z + v.w*v.w;
    ss = warp_sum(ss);
    float scale = fminf(1.0f, 1.0f / (sqrtf(ss) + 1e-7f));
    float4 o = make_float4(v.x*scale, v.y*scale, v.z*scale, v.w*scale);
    *(uint2*)(g_hb + (size_t)warp * 64 + lane * 2) =
        make_uint2(packbf(o.x, o.y), packbf(o.z, o.w));
}

// ---------------- zero kernels -----------------------------------------------
__global__ void zero_deg_kernel() {
    int i = blockIdx.x * blockDim.x + threadIdx.x;
    if (i < N_NODES) g_deg[i] = 0;
}
__global__ void zero_pool_kernel() {
    int i = threadIdx.x + blockIdx.x * blockDim.x;
    if (i < N_GRAPHS * HIDDEN) g_pool[i] = 0.f;
    if (i < N_GRAPHS) g_cnt[i] = 0.f;
}

// ---------------- CSR build ---------------------------------------------------
__global__ void hist_kernel(const int* __restrict__ eidx) {
    int e4 = blockIdx.x * blockDim.x + threadIdx.x;
    if (e4 >= N_EDGES / 4) return;
    int4 d = __ldg((const int4*)(eidx + N_EDGES) + e4);
    atomicAdd(&g_deg[d.x], 1);
    atomicAdd(&g_deg[d.y], 1);
    atomicAdd(&g_deg[d.z], 1);
    atomicAdd(&g_deg[d.w], 1);
}

#define SCCH 512
#define SCB  ((N_NODES + SCCH - 1) / SCCH)   // 196
__global__ void scanA_kernel() {
    __shared__ int s[256];
    int b = blockIdx.x, t = threadIdx.x;
    int base = b * SCCH;
    int v = 0;
    #pragma unroll
    for (int i = 0; i < 2; i++) {
        int j = base + t + i * 256;
        if (j < N_NODES) v += g_deg[j];
    }
    s[t] = v;
    __syncthreads();
    #pragma unroll
    for (int off = 128; off > 0; off >>= 1) {
        if (t < off) s[t] += s[t + off];
        __syncthreads();
    }
    if (t == 0) g_bsum[b] = s[0];
}
__global__ void scanB_kernel() {
    __shared__ int s[256];
    int t = threadIdx.x;
    int v = (t < SCB) ? g_bsum[t] : 0;
    s[t] = v;
    __syncthreads();
    #pragma unroll
    for (int off = 1; off < 256; off <<= 1) {
        int u = (t >= off) ? s[t - off] : 0;
        __syncthreads();
        s[t] += u;
        __syncthreads();
    }
    if (t < SCB) g_boff[t] = s[t] - v;            // exclusive
    if (t == 255) g_rowstart[N_NODES] = s[255];   // total
}
__global__ void scanC_kernel() {
    __shared__ int s[256];
    int b = blockIdx.x, t = threadIdx.x;
    int n0 = b * SCCH + 2 * t;
    int n1 = n0 + 1;
    int d0 = (n0 < N_NODES) ? g_deg[n0] : 0;
    int d1 = (n1 < N_NODES) ? g_deg[n1] : 0;
    int pair = d0 + d1;
    s[t] = pair;
    __syncthreads();
    #pragma unroll
    for (int off = 1; off < 256; off <<= 1) {
        int u = (t >= off) ? s[t - off] : 0;
        __syncthreads();
        s[t] += u;
        __syncthreads();
    }
    int off0 = g_boff[b] + s[t] - pair;
    if (n0 < N_NODES) { g_rowstart[n0] = off0;      g_cursor[n0] = off0; }
    if (n1 < N_NODES) { g_rowstart[n1] = off0 + d0; g_cursor[n1] = off0 + d0; }
}

__global__ void reorder_kernel(const int* __restrict__ eidx,
                               const float* __restrict__ ew) {
    int e4 = blockIdx.x * blockDim.x + threadIdx.x;
    if (e4 >= N_EDGES / 4) return;
    int4   s4 = __ldg((const int4*)eidx + e4);
    int4   d4 = __ldg((const int4*)(eidx + N_EDGES) + e4);
    float4 w4 = __ldg((const float4*)ew + e4);
    int p;
    p = atomicAdd(&g_cursor[d4.x], 1); g_csr[p] = make_int2(s4.x, __float_as_int(w4.x));
    p = atomicAdd(&g_cursor[d4.y], 1); g_csr[p] = make_int2(s4.y, __float_as_int(w4.y));
    p = atomicAdd(&g_cursor[d4.z], 1); g_csr[p] = make_int2(s4.z, __float_as_int(w4.z));
    p = atomicAdd(&g_cursor[d4.w], 1); g_csr[p] = make_int2(s4.w, __float_as_int(w4.w));
}

// ---------------- CSR aggregation, bf16 gather, warp per node ---------------
__global__ void __launch_bounds__(256)
agg_csr_kernel() {
    int warp = (blockIdx.x * blockDim.x + threadIdx.x) >> 5;
    int lane = threadIdx.x & 31;
    if (warp >= N_NODES) return;
    int s0 = g_rowstart[warp], s1 = g_rowstart[warp + 1];
    float4 acc = make_float4(0.f, 0.f, 0.f, 0.f);

    for (int base = s0; base < s1; base += 32) {
        int m = min(32, s1 - base);
        int2 e = make_int2(0, 0);
        if (base + lane < s1) e = __ldg(&g_csr[base + lane]);

        int i = 0;
        for (; i + 3 < m; i += 4) {
            int   sA = __shfl_sync(0xffffffffu, e.x, i);
            float wA = __int_as_float(__shfl_sync(0xffffffffu, e.y, i));
            int   sB = __shfl_sync(0xffffffffu, e.x, i + 1);
            float wB = __int_as_float(__shfl_sync(0xffffffffu, e.y, i + 1));
            int   sC = __shfl_sync(0xffffffffu, e.x, i + 2);
            float wC = __int_as_float(__shfl_sync(0xffffffffu, e.y, i + 2));
            int   sD = __shfl_sync(0xffffffffu, e.x, i + 3);
            float wD = __int_as_float(__shfl_sync(0xffffffffu, e.y, i + 3));
            uint2 uA = __ldg((const uint2*)(g_hb + (size_t)sA * 64) + lane);
            uint2 uB = __ldg((const uint2*)(g_hb + (size_t)sB * 64) + lane);
            uint2 uC = __ldg((const uint2*)(g_hb + (size_t)sC * 64) + lane);
            uint2 uD = __ldg((const uint2*)(g_hb + (size_t)sD * 64) + lane);
            accum_bf(acc, uA, wA);
            accum_bf(acc, uB, wB);
            accum_bf(acc, uC, wC);
            accum_bf(acc, uD, wD);
        }
        for (; i < m; i++) {
            int   se = __shfl_sync(0xffffffffu, e.x, i);
            float we = __int_as_float(__shfl_sync(0xffffffffu, e.y, i));
            uint2 ue = __ldg((const uint2*)(g_hb + (size_t)se * 64) + lane);
            accum_bf(acc, ue, we);
        }
    }
    uint2 outp = make_uint2(packbf(acc.x, acc.y), packbf(acc.z, acc.w));
    __stcs((uint2*)(g_aggb + (size_t)warp * 64) + lane, outp);
}

// ---------------- 2-pass bf16 tensor-core dual GEMM --------------------------
// out = relu([aggb | hb](100k x 256, bf16) @ (Bhi + Blo)(256 x 128) + bias)
// Block: 128 rows x 64 cols; 8 warps = 4(M) x 2(N); warp tile 32x32.
// B smem layout: per column, k-words permuted pos = g*8 + (i&3)*2 + (i>>2)
// so each MMA fragment pair (W, W+4) is adjacent -> LDS.64.
// SB_COL_W must be EVEN (8-byte alignment of uint2 loads); 136 % 32 = 8 gives
// conflict-free fragment reads (banks 8q+2r distinct across a 16-lane phase).
#define SB_COL_W      136                      // 128 data words + 8 pad (even)
#define SB_PLANE_W    (64 * SB_COL_W)          // 8704 words
#define SA_ROW_W      12                       // 8 data words + 4 pad
#define SA_PLANE_W    (128 * SA_ROW_W)         // 1536 words
#define GEMM_SMEM_BYTES ((2 * SB_PLANE_W + 2 * SA_PLANE_W) * 4)   // 81920

__global__ void __launch_bounds__(256, 2)
linear_bf16_kernel(const unsigned* __restrict__ aggb,
                   const unsigned* __restrict__ hb,
                   const __nv_bfloat16* __restrict__ bhi,
                   const __nv_bfloat16* __restrict__ blo,
                   const float* __restrict__ bias,
                   unsigned* __restrict__ outB) {   // packed bf16 out
    extern __shared__ char smem_raw[];
    unsigned* sBhi = (unsigned*)smem_raw;
    unsigned* sBlo = sBhi + SB_PLANE_W;
    unsigned* sA   = sBlo + SB_PLANE_W;

    int tid = threadIdx.x, lane = tid & 31, warp = tid >> 5;
    int warpM = warp & 3, warpN = warp >> 2;
    int tileM = blockIdx.x >> 1;
    int nb = (blockIdx.x & 1) * 64;
    int rowBase = tileM * 128;

    // ---- load B 64-col slice (hi+lo) into smem, permuted for LDS.64 ----
    const uint4* srcHi = (const uint4*)(bhi + (size_t)nb * 256);
    const uint4* srcLo = (const uint4*)(blo + (size_t)nb * 256);
    #pragma unroll
    for (int it = 0; it < 8; it++) {
        int idx = it * 256 + tid;              // 2048 uint4 total
        int col = idx >> 5, q = idx & 31;      // q: which uint4 (4 words)
        uint4 v = __ldg(srcHi + col * 32 + q);
        uint4 w = __ldg(srcLo + col * 32 + q);
        unsigned* dh = sBhi + col * SB_COL_W;
        unsigned* dl = sBlo + col * SB_COL_W;
        int W = q * 4;                         // first word index
        #pragma unroll
        for (int u = 0; u < 4; u++) {
            int Wk = W + u;
            int pos = (Wk & ~7) + ((Wk & 3) << 1) + ((Wk >> 2) & 1);
            unsigned hv = (u == 0) ? v.x : (u == 1) ? v.y : (u == 2) ? v.z : v.w;
            unsigned lv = (u == 0) ? w.x : (u == 1) ? w.y : (u == 2) ? w.z : w.w;
            dh[pos] = hv;
            dl[pos] = lv;
        }
    }

    // ---- A stage loader: stage s covers k = s*16 .. s*16+15 (8 words/row) --
    int rA = tid >> 1, qA = tid & 1;          // row 0..127, half 0..1
    uint4 cur, pre;
    auto loadA = [&](int s, uint4& dst) {
        const unsigned* src = (s < 8) ? aggb : hb;
        int woff = (s & 7) * 8 + qA * 4;
        int node = rowBase + rA;
        dst = make_uint4(0u, 0u, 0u, 0u);
        if (node < N_NODES)
            dst = __ldg((const uint4*)(src + (size_t)node * 64 + woff));
    };
    auto storeA = [&](int buf, const uint4& v) {
        *(uint4*)(sA + buf * SA_PLANE_W + rA * SA_ROW_W + qA * 4) = v;
    };

    loadA(0, cur);
    storeA(0, cur);
    __syncthreads();

    float4 acc[2][4];
    #pragma unroll
    for (int mt = 0; mt < 2; mt++)
        #pragma unroll
        for (int j = 0; j < 4; j++)
            acc[mt][j] = make_float4(0.f, 0.f, 0.f, 0.f);

    for (int s = 0; s < 16; s++) {
        if (s < 15) loadA(s + 1, pre);

        const unsigned* Ab = sA + (s & 1) * SA_PLANE_W;

        unsigned ah[2][4];
        #pragma unroll
        for (int mt = 0; mt < 2; mt++) {
            int r0 = warpM * 32 + mt * 16 + (lane >> 2);
            int w0 = lane & 3;
            ah[mt][0] = Ab[r0 * SA_ROW_W + w0];
            ah[mt][1] = Ab[(r0 + 8) * SA_ROW_W + w0];
            ah[mt][2] = Ab[r0 * SA_ROW_W + w0 + 4];
            ah[mt][3] = Ab[(r0 + 8) * SA_ROW_W + w0 + 4];
        }
        uint2 bh[4], bl[4];
        #pragma unroll
        for (int j = 0; j < 4; j++) {
            int c = warpN * 32 + j * 8 + (lane >> 2);
            int w = c * SB_COL_W + s * 8 + (lane & 3) * 2;
            bh[j] = *(const uint2*)(sBhi + w);
            bl[j] = *(const uint2*)(sBlo + w);
        }
        #pragma unroll
        for (int mt = 0; mt < 2; mt++)
            #pragma unroll
            for (int j = 0; j < 4; j++) {
                mma_bf16(acc[mt][j], ah[mt], bh[j].x, bh[j].y);
                mma_bf16(acc[mt][j], ah[mt], bl[j].x, bl[j].y);
            }

        if (s < 15) storeA((s + 1) & 1, pre);
        __syncthreads();
    }

    // ---- epilogue: bias + relu + packed bf16 store ----
    #pragma unroll
    for (int mt = 0; mt < 2; mt++) {
        #pragma unroll
        for (int j = 0; j < 4; j++) {
            int col = nb + warpN * 32 + j * 8 + (lane & 3) * 2;
            float b0 = __ldg(bias + col);
            float b1 = __ldg(bias + col + 1);
            int row0 = rowBase + warpM * 32 + mt * 16 + (lane >> 2);
            int row1 = row0 + 8;
            float4 c = acc[mt][j];
            if (row0 < N_NODES)
                outB[(size_t)row0 * 64 + (col >> 1)] =
                    packbf(fmaxf(c.x + b0, 0.f), fmaxf(c.y + b1, 0.f));
            if (row1 < N_NODES)
                outB[(size_t)row1 * 64 + (col >> 1)] =
                    packbf(fmaxf(c.z + b0, 0.f), fmaxf(c.w + b1, 0.f));
        }
    }
}

// ---------------- segmented mean-pool from packed bf16 (batch sorted) -------
#define POOL_CHUNK 256
__global__ void pool_kernel(const int* __restrict__ batch,
                            const unsigned* __restrict__ hb) {
    int n0 = blockIdx.x * POOL_CHUNK;
    int n1 = min(n0 + POOL_CHUNK, N_NODES);
    if (n0 >= N_NODES) return;
    int t = threadIdx.x;                    // 64 threads: word t = dims 2t,2t+1
    float ax = 0.f, ay = 0.f, cnt = 0.f;
    int cur = batch[n0];
    for (int n = n0; n < n1; n++) {
        int b = batch[n];
        if (b != cur) {
            atomicAdd(&g_pool[cur * HIDDEN + 2 * t], ax);
            atomicAdd(&g_pool[cur * HIDDEN + 2 * t + 1], ay);
            if (t == 0) atomicAdd(&g_cnt[cur], cnt);
            ax = 0.f; ay = 0.f; cnt = 0.f; cur = b;
        }
        unsigned u = hb[(size_t)n * 64 + t];
        float2 f = __bfloat1622float2(*reinterpret_cast<__nv_bfloat162*>(&u));
        ax += f.x; ay += f.y; cnt += 1.f;
    }
    atomicAdd(&g_pool[cur * HIDDEN + 2 * t], ax);
    atomicAdd(&g_pool[cur * HIDDEN + 2 * t + 1], ay);
    if (t == 0) atomicAdd(&g_cnt[cur], cnt);
}

// ---------------- classifier -------------------------------------------------
__global__ void __launch_bounds__(256)
classifier_kernel(const float* __restrict__ cls1_w,
                  const float* __restrict__ cls1_b,
                  const float* __restrict__ cls2_w,
                  const float* __restrict__ cls2_b,
                  float* __restrict__ out) {
    __shared__ float s_w1[L1DIM * HIDDEN];
    __shared__ float s_b1[L1DIM];
    __shared__ float s_w2[2 * L1DIM];
    __shared__ float s_b2[2];

    for (int i = threadIdx.x; i < L1DIM * HIDDEN; i += blockDim.x)
        s_w1[i] = cls1_w[i];
    if (threadIdx.x < L1DIM) s_b1[threadIdx.x] = cls1_b[threadIdx.x];
    if (threadIdx.x < 2 * L1DIM) s_w2[threadIdx.x] = cls2_w[threadIdx.x];
    if (threadIdx.x < 2) s_b2[threadIdx.x] = cls2_b[threadIdx.x];
    __syncthreads();

    int g = blockIdx.x * 8 + (threadIdx.x >> 5);
    int lane = threadIdx.x & 31;
    if (g >= N_GRAPHS) return;

    float c = fmaxf(g_cnt[g], 1.0f);
    float4 p = ((const float4*)(g_pool + g * HIDDEN))[lane];
    float inv = 1.0f / c;
    p.x *= inv; p.y *= inv; p.z *= inv; p.w *= inv;

    float z1a = 0.f, z1b = 0.f;
    const float4* w14 = (const float4*)s_w1;
    #pragma unroll 4
    for (int j = 0; j < L1DIM; j++) {
        float4 w = w14[j * 32 + lane];
        float s = p.x*w.x + p.y*w.y + p.z*w.z + p.w*w.w;
        s = warp_sum(s);
        float v = fmaxf(s + s_b1[j], 0.f);
        if (j < 32) { if (lane == j)      z1a = v; }
        else        { if (lane == j - 32) z1b = v; }
    }
    float t0 = s_w2[lane] * z1a + s_w2[lane + 32] * z1b;
    float t1 = s_w2[L1DIM + lane] * z1a + s_w2[L1DIM + lane + 32] * z1b;
    t0 = warp_sum(t0);
    t1 = warp_sum(t1);
    if (lane == 0) {
        float z0 = t0 + s_b2[0];
        float z1 = t1 + s_b2[1];
        float m = fmaxf(z0, z1);
        float e0 = expf(z0 - m), e1 = expf(z1 - m);
        float d = e0 + e1;
        out[g * 2 + 0] = e0 / d;
        out[g * 2 + 1] = e1 / d;
    }
}

// ---------------- launch ----------------------------------------------------
extern "C" void kernel_launch(void* const* d_in, const int* in_sizes, int n_in,
                              void* d_out, int out_size) {
    const int*   x       = (const int*)  d_in[0];
    const int*   eidx    = (const int*)  d_in[1];
    const float* eweight = (const float*)d_in[2];
    const int*   batch   = (const int*)  d_in[3];
    const float* emb_w   = (const float*)d_in[4];
    const float* w1_rel  = (const float*)d_in[5];
    const float* b1_rel  = (const float*)d_in[6];
    const float* w1_root = (const float*)d_in[7];
    const float* w2_rel  = (const float*)d_in[8];
    const float* b2_rel  = (const float*)d_in[9];
    const float* w2_root = (const float*)d_in[10];
    const float* cls1_w  = (const float*)d_in[11];
    const float* cls1_b  = (const float*)d_in[12];
    const float* cls2_w  = (const float*)d_in[13];
    const float* cls2_b  = (const float*)d_in[14];
    float* out = (float*)d_out;

    unsigned *p_hb, *p_aggb;
    __nv_bfloat16 *p_b1hi, *p_b1lo, *p_b2hi, *p_b2lo;
    cudaGetSymbolAddress((void**)&p_hb,   g_hb);
    cudaGetSymbolAddress((void**)&p_aggb, g_aggb);
    cudaGetSymbolAddress((void**)&p_b1hi, g_b1hi);
    cudaGetSymbolAddress((void**)&p_b1lo, g_b1lo);
    cudaGetSymbolAddress((void**)&p_b2hi, g_b2hi);
    cudaGetSymbolAddress((void**)&p_b2lo, g_b2lo);

    static cudaStream_t s2 = nullptr;
    static cudaEvent_t evFork = nullptr, evJoin = nullptr;
    static int smem_set = 0;
    if (!smem_set) {
        cudaFuncSetAttribute(linear_bf16_kernel,
                             cudaFuncAttributeMaxDynamicSharedMemorySize,
                             GEMM_SMEM_BYTES);
        cudaStreamCreateWithFlags(&s2, cudaStreamNonBlocking);
        cudaEventCreateWithFlags(&evFork, cudaEventDisableTiming);
        cudaEventCreateWithFlags(&evJoin, cudaEventDisableTiming);
        smem_set = 1;
    }

    // ---- fork: CSR build on side stream, embedding path on main stream ----
    cudaEventRecord(evFork, 0);
    cudaStreamWaitEvent(s2, evFork, 0);

    // side stream: CSR build
    zero_deg_kernel<<<(N_NODES + 255) / 256, 256, 0, s2>>>();
    hist_kernel<<<(N_EDGES / 4 + 255) / 256, 256, 0, s2>>>(eidx);
    scanA_kernel<<<SCB, 256, 0, s2>>>();
    scanB_kernel<<<1, 256, 0, s2>>>();
    scanC_kernel<<<SCB, 256, 0, s2>>>();
    reorder_kernel<<<(N_EDGES / 4 + 255) / 256, 256, 0, s2>>>(eidx, eweight);
    cudaEventRecord(evJoin, s2);

    // main stream: weights + embedding + pool zero
    prep_weights_kernel<<<64, 256>>>(w1_rel, w1_root, w2_rel, w2_root);
    zero_pool_kernel<<<(N_GRAPHS * HIDDEN + 255) / 256, 256>>>();
    embed_kernel<<<(N_NODES + 7) / 8, 256>>>(x, emb_w);

    // join
    cudaStreamWaitEvent(0, evJoin, 0);

    int nTiles = (N_NODES + 127) / 128;
    // layer 1: out -> g_hb (bf16)
    agg_csr_kernel<<<(N_NODES * 32 + 255) / 256, 256>>>();
    linear_bf16_kernel<<<nTiles * 2, 256, GEMM_SMEM_BYTES>>>(
        p_aggb, p_hb, p_b1hi, p_b1lo, b1_rel, p_hb);
    // layer 2: out -> g_aggb (bf16; safe row-wise self-overwrite)
    agg_csr_kernel<<<(N_NODES * 32 + 255) / 256, 256>>>();
    linear_bf16_kernel<<<nTiles * 2, 256, GEMM_SMEM_BYTES>>>(
        p_aggb, p_hb, p_b2hi, p_b2lo, b2_rel, p_aggb);

    // pool + classify
    pool_kernel<<<(N_NODES + POOL_CHUNK - 1) / POOL_CHUNK, 64>>>(batch, p_aggb);
    classifier_kernel<<<32, 256>>>(cls1_w, cls1_b, cls2_w, cls2_b, out);
}